// round 8
// baseline (speedup 1.0000x reference)
#include <cuda_runtime.h>
#include <math.h>
#include <stdint.h>

// Problem constants
#define NN   30000
#define NE   60000
#define FEAT 256
#define HID  1024
#define OUTD 256
#define RANK 64
#define NC   1408   // HID + OUTD + RANK + 64 pad

// ---------------- scratch (device globals) ----------------
__device__ float g_embR    [NN * FEAT];
__device__ float g_emb_new [NN * RANK];
__device__ float g_hidden  [NN * HID];    // stored tf32-rounded
__device__ float g_emb_new2[NN * OUTD];
__device__ float g_residual[NN * OUTD];
__device__ float g_tee     [NE * 4 * RANK];
__device__ float g_esum2   [NE * OUTD];
__device__ float g_nodeacc [NN * OUTD];
__device__ float g_accR    [NN * RANK];   // stored tf32-rounded
__device__ int   g_offs    [NN + 1];
__device__ int   g_cursor  [NN];
__device__ int   g_csr     [NE * 4];
// K-major tf32-rounded weights
__device__ float g_WtC [NC * FEAT];       // [Wt1 ; WtA ; WtP ; 0pad]  1408 x 256
__device__ float g_Wt2 [OUTD * HID];
__device__ float g_WtQ [OUTD * RANK];
__device__ float g_biasC [NC];

// ---------------- helpers ----------------
__device__ __forceinline__ uint32_t smem_u32(const void* p) {
    uint32_t a;
    asm("{ .reg .u64 t; cvta.to.shared.u64 t, %1; cvt.u32.u64 %0, t; }" : "=r"(a) : "l"(p));
    return a;
}
__device__ __forceinline__ float tf32r(float x) {
    uint32_t u;
    asm("cvt.rna.tf32.f32 %0, %1;" : "=r"(u) : "f"(x));
    return __uint_as_float(u);
}
__device__ __forceinline__ void cp16(uint32_t dst, const void* src, int szbytes) {
    asm volatile("cp.async.ca.shared.global [%0], [%1], 16, %2;"
                 :: "r"(dst), "l"(src), "r"(szbytes) : "memory");
}
#define CP_COMMIT() asm volatile("cp.async.commit_group;" ::: "memory")
#define CP_WAIT(n)  asm volatile("cp.async.wait_group %0;" :: "n"(n) : "memory")

__device__ __forceinline__ void mma16n8k8(float* d, const uint32_t* a, const uint32_t* b) {
    asm volatile(
        "mma.sync.aligned.m16n8k8.row.col.f32.tf32.tf32.f32 "
        "{%0,%1,%2,%3}, {%4,%5,%6,%7}, {%8,%9}, {%0,%1,%2,%3};"
        : "+f"(d[0]), "+f"(d[1]), "+f"(d[2]), "+f"(d[3])
        : "r"(a[0]), "r"(a[1]), "r"(a[2]), "r"(a[3]), "r"(b[0]), "r"(b[1]));
}

// ---------------- mega-prep: transposes + bias folds + emb round + pad zero ----------------
// blocks [0,608): weight transposes; [608,616): biasC; [616,680): WtC pad zero;
// [680, 680+n4/256): embedding tf32 round.
__global__ void prep_all(const float* __restrict__ emb,
                         const float* __restrict__ p2W1, const float* __restrict__ p2W2,
                         const float* __restrict__ aW,   const float* __restrict__ pW,
                         const float* __restrict__ qW,
                         const float* __restrict__ p2b1, const float* __restrict__ ab_,
                         const float* __restrict__ pb_,  int n4)
{
    __shared__ float t[32][33];
    const int bx = blockIdx.x;
    const int tid = threadIdx.x;
    if (bx < 608) {
        const float* W; float* Wt; int K, N, t0;
        if      (bx < 256) { W = p2W1; Wt = g_WtC;              K = FEAT; N = HID;  t0 = 0;   }
        else if (bx < 512) { W = p2W2; Wt = g_Wt2;              K = HID;  N = OUTD; t0 = 256; }
        else if (bx < 576) { W = aW;   Wt = g_WtC + HID * FEAT; K = FEAT; N = OUTD; t0 = 512; }
        else if (bx < 592) { W = pW;   Wt = g_WtC + (HID + OUTD) * FEAT; K = FEAT; N = RANK; t0 = 576; }
        else               { W = qW;   Wt = g_WtQ;              K = RANK; N = OUTD; t0 = 592; }
        int tt = bx - t0;
        int tiles_n = N >> 5;
        int n0 = (tt % tiles_n) * 32, k0 = (tt / tiles_n) * 32;
        int tx = tid & 31, ty = tid >> 5;
        for (int i = ty; i < 32; i += 8)
            t[i][tx] = W[(size_t)(k0 + i) * N + n0 + tx];
        __syncthreads();
        for (int i = ty; i < 32; i += 8)
            Wt[(size_t)(n0 + i) * K + k0 + tx] = tf32r(t[tx][i]);
    } else if (bx < 616) {
        int i = (bx - 608) * 256 + tid;
        if      (i < HID)              g_biasC[i] = p2b1[i] + p2W1[FEAT * HID + i];
        else if (i < HID + OUTD)       g_biasC[i] = ab_[i - HID] + aW[FEAT * OUTD + (i - HID)];
        else if (i < HID + OUTD + RANK) g_biasC[i] = pb_[i - HID - OUTD] + pW[FEAT * RANK + (i - HID - OUTD)];
        else if (i < NC)               g_biasC[i] = 0.f;
    } else if (bx < 680) {
        int i = (bx - 616) * 256 + tid;     // 64*256 = 16384 pad floats
        g_WtC[(size_t)(HID + OUTD + RANK) * FEAT + i] = 0.f;
    } else {
        int i = (bx - 680) * 256 + tid;
        if (i < n4) {
            float4 v = ((const float4*)emb)[i];
            v.x = tf32r(v.x); v.y = tf32r(v.y); v.z = tf32r(v.z); v.w = tf32r(v.w);
            ((float4*)g_embR)[i] = v;
        }
    }
}

// ---------------- CSR offsets: two-pass coarsened scan (unrolled, int4) ----------------
__global__ __launch_bounds__(1024)
void scan_offsets(const int* __restrict__ deg, int* __restrict__ offs,
                  int* __restrict__ cursor, int N)
{
    constexpr int CE = 32;
    const int tid = threadIdx.x;
    const int start = tid * CE;

    // pass 1: per-thread sum with independent vector loads
    int local = 0;
    if (start < N) {
        #pragma unroll
        for (int j = 0; j < CE; j += 4) {
            int i = start + j;
            if (i + 3 < N) {
                int4 v = *(const int4*)(deg + i);
                local += v.x + v.y + v.z + v.w;
            } else {
                #pragma unroll
                for (int k = 0; k < 4; k++) if (i + k < N) local += deg[i + k];
            }
        }
    }
    // block exclusive scan of per-thread sums
    __shared__ int warpsum[32];
    int lane = tid & 31, w = tid >> 5;
    int x = local;
    #pragma unroll
    for (int o = 1; o < 32; o <<= 1) { int y = __shfl_up_sync(~0u, x, o); if (lane >= o) x += y; }
    if (lane == 31) warpsum[w] = x;
    __syncthreads();
    if (w == 0) {
        int s = warpsum[lane];
        #pragma unroll
        for (int o = 1; o < 32; o <<= 1) { int y = __shfl_up_sync(~0u, s, o); if (lane >= o) s += y; }
        warpsum[lane] = s;
    }
    __syncthreads();
    int base = x - local + (w > 0 ? warpsum[w - 1] : 0);

    // pass 2: emit running offsets (deg re-loads are L1-hot)
    if (start < N) {
        int run = base;
        #pragma unroll
        for (int j = 0; j < CE; j++) {
            int i = start + j;
            if (i < N) { offs[i] = run; cursor[i] = 0; run += deg[i]; }
        }
        if (tid == (N - 1) / CE) offs[N] = run;
    }
}

__global__ void csr_fill(const int* __restrict__ inc_node, const int* __restrict__ inc_edge,
                         const int* __restrict__ inc_slot, int NINC)
{
    int i = blockIdx.x * blockDim.x + threadIdx.x;
    if (i < NINC) {
        int n = inc_node[i];
        int p = atomicAdd(&g_cursor[n], 1);
        g_csr[g_offs[n] + p] = (inc_edge[i] << 2) | inc_slot[i];
    }
}

// ---------------- tensor-core tf32 GEMM (mma.sync; 128 x NT tile, occ 2) ----------------
// mode 0: C = acc + bias
// mode 2: C = relu((acc + addSrc)/deg + bias) + resid
// mode 3: 3-way split: col<1024 -> relu,tf32r -> C (hidden, stride HID)
//                      col<1280 -> relu -> C2 (residual, stride OUTD)
//                      col<1344 -> plain -> C3 (emb_new, stride RANK); col>=1344 skip
template<int NT>
__global__ __launch_bounds__(256, 2)
void mma_gemm(const float* __restrict__ A, const float* __restrict__ Bt,
              const float* __restrict__ bias,
              float* __restrict__ C, float* __restrict__ C2, float* __restrict__ C3,
              int M, int N, int K, int mode,
              const float* __restrict__ addSrc, const float* __restrict__ resid,
              const int* __restrict__ degv)
{
    constexpr int ST = 36;
    constexpr int NTILES = NT / 16;
    extern __shared__ float dyn[];
    float* Asm = dyn;
    float* Bsm = dyn + 2 * 128 * ST;

    const int tid  = threadIdx.x;
    const int wid  = tid >> 5;
    const int lane = tid & 31;
    const int grp  = lane >> 2;
    const int tig  = lane & 3;
    const int warpM = (wid & 3) * 32;
    const int warpN = (wid >> 2) * (NT / 2);
    const int rowBase = blockIdx.y * 128;
    const int colBase = blockIdx.x * NT;

    float acc[2][NTILES][4];
    #pragma unroll
    for (int mt = 0; mt < 2; mt++)
        #pragma unroll
        for (int nt = 0; nt < NTILES; nt++)
            #pragma unroll
            for (int i = 0; i < 4; i++) acc[mt][nt][i] = 0.f;

    const uint32_t asm_base = smem_u32(Asm);
    const uint32_t bsm_base = smem_u32(Bsm);

    auto loadChunk = [&](int c, int buf) {
        #pragma unroll
        for (int i = 0; i < 4; i++) {
            int idx = tid + (i << 8);
            int r = idx >> 3, f4 = idx & 7;
            int gr = rowBase + r;
            const float* src = A + (size_t)gr * K + (c << 5) + (f4 << 2);
            uint32_t dst = asm_base + (buf * 128 * ST + r * ST + (f4 << 2)) * 4;
            cp16(dst, src, gr < M ? 16 : 0);
        }
        #pragma unroll
        for (int i = 0; i < NT / 32; i++) {
            int idx = tid + (i << 8);
            int r = idx >> 3, f4 = idx & 7;
            const float* src = Bt + (size_t)(colBase + r) * K + (c << 5) + (f4 << 2);
            uint32_t dst = bsm_base + (buf * NT * ST + r * ST + (f4 << 2)) * 4;
            cp16(dst, src, 16);
        }
        CP_COMMIT();
    };

    const int nch = K >> 5;
    loadChunk(0, 0);

    for (int c = 0; c < nch; ++c) {
        const int buf = c & 1;
        if (c + 1 < nch) { loadChunk(c + 1, buf ^ 1); CP_WAIT(1); }
        else             { CP_WAIT(0); }
        __syncthreads();

        const float* ab = Asm + buf * 128 * ST;
        const float* bb = Bsm + buf * NT * ST;
        #pragma unroll
        for (int ks = 0; ks < 4; ++ks) {
            const int kb = ks << 3;
            uint32_t afr[2][4];
            #pragma unroll
            for (int mt = 0; mt < 2; mt++) {
                int base = (warpM + mt * 16 + grp) * ST + kb + tig;
                afr[mt][0] = __float_as_uint(ab[base]);
                afr[mt][1] = __float_as_uint(ab[base + 8 * ST]);
                afr[mt][2] = __float_as_uint(ab[base + 4]);
                afr[mt][3] = __float_as_uint(ab[base + 8 * ST + 4]);
            }
            uint32_t bfr[NTILES][2];
            #pragma unroll
            for (int nt = 0; nt < NTILES; nt++) {
                int base = (warpN + nt * 8 + grp) * ST + kb + tig;
                bfr[nt][0] = __float_as_uint(bb[base]);
                bfr[nt][1] = __float_as_uint(bb[base + 4]);
            }
            #pragma unroll
            for (int mt = 0; mt < 2; mt++)
                #pragma unroll
                for (int nt = 0; nt < NTILES; nt++)
                    mma16n8k8(acc[mt][nt], afr[mt], bfr[nt]);
        }
        __syncthreads();
    }

    #pragma unroll
    for (int mt = 0; mt < 2; mt++) {
        #pragma unroll
        for (int nt = 0; nt < NTILES; nt++) {
            int col = colBase + warpN + nt * 8 + (tig << 1);
            float b0 = bias[col], b1 = bias[col + 1];
            #pragma unroll
            for (int h = 0; h < 2; h++) {
                int row = rowBase + warpM + mt * 16 + grp + h * 8;
                if (row >= M) continue;
                float v0 = acc[mt][nt][2 * h];
                float v1 = acc[mt][nt][2 * h + 1];
                if (mode == 3) {
                    if (col < HID) {
                        v0 = fmaxf(v0 + b0, 0.f); v1 = fmaxf(v1 + b1, 0.f);
                        *(float2*)(C + (size_t)row * HID + col) =
                            make_float2(tf32r(v0), tf32r(v1));
                    } else if (col < HID + OUTD) {
                        v0 = fmaxf(v0 + b0, 0.f); v1 = fmaxf(v1 + b1, 0.f);
                        *(float2*)(C2 + (size_t)row * OUTD + (col - HID)) = make_float2(v0, v1);
                    } else if (col < HID + OUTD + RANK) {
                        *(float2*)(C3 + (size_t)row * RANK + (col - HID - OUTD)) =
                            make_float2(v0 + b0, v1 + b1);
                    }
                } else if (mode == 2) {
                    float rd = 1.0f / (float)degv[row];
                    size_t base = (size_t)row * N + col;
                    v0 = fmaxf((v0 + addSrc[base])     * rd + b0, 0.f) + resid[base];
                    v1 = fmaxf((v1 + addSrc[base + 1]) * rd + b1, 0.f) + resid[base + 1];
                    *(float2*)(C + base) = make_float2(v0, v1);
                } else {
                    *(float2*)(C + (size_t)row * N + col) = make_float2(v0 + b0, v1 + b1);
                }
            }
        }
    }
}

// ---------------- edge kernel: 2 edges per 256-thread block ----------------
__global__ __launch_bounds__(256)
void edge_kernel(const float* __restrict__ global_emb,
                 const int* __restrict__ edge_nodes,
                 const int* __restrict__ edge_size,
                 const int* __restrict__ node_degree,
                 int E)
{
    __shared__ int   s_nodes[2][4];
    __shared__ float s_scale[2][4];
    __shared__ int   s_size[2];

    const int half = threadIdx.x >> 7;
    const int lt   = threadIdx.x & 127;
    const int e    = blockIdx.x * 2 + half;
    const bool active = (e < E);

    if (active && lt < 4) {
        int sz = edge_size[e];
        if (lt == 0) s_size[half] = sz;
        int n = edge_nodes[e * 4 + lt];
        s_nodes[half][lt] = n;
        float a = (sz == 1) ? 1.0f : (sz <= 3 ? (1.0f / 3.0f) : 0.25f);
        s_scale[half][lt] = __powf((float)node_degree[n], a);
    }
    __syncthreads();
    if (!active) return;

    const int sz = s_size[half];
    const int k = 4 - sz;
    const float invf = (sz == 3) ? 0.5f : (sz == 4 ? (1.0f / 6.0f) : 1.0f);

    if (lt < RANK) {
        const int r = lt;
        float g = global_emb[r];
        float gf = (k == 0) ? 1.0f : (k == 1 ? g : g * g);
        float t[4];
        #pragma unroll
        for (int s = 0; s < 4; s++)
            t[s] = (s < sz) ? s_scale[half][s] * g_emb_new[(size_t)s_nodes[half][s] * RANK + r] : 1.0f;
        float loo[4];
        loo[0] = t[1] * t[2] * t[3];
        loo[1] = t[0] * t[2] * t[3];
        loo[2] = t[0] * t[1] * t[3];
        loo[3] = t[0] * t[1] * t[2];
        float f = gf * invf;
        for (int s = 0; s < sz; s++)
            g_tee[((size_t)e * 4 + s) * RANK + r] = tanhf(loo[s] * f);
    }

    {
        float sum0 = 0.f, sum1 = 0.f;
        for (int s = 0; s < sz; s++) {
            const float* row = g_emb_new2 + (size_t)s_nodes[half][s] * OUTD;
            sum0 += row[lt];
            sum1 += row[lt + 128];
        }
        g_esum2[(size_t)e * OUTD + lt]       = fmaxf(sum0, 0.f);
        g_esum2[(size_t)e * OUTD + lt + 128] = fmaxf(sum1, 0.f);
    }
}

// ---------------- node-major gather (unrolled x2 for MLP) ----------------
__global__ __launch_bounds__(256)
void node_gather()
{
    int n = blockIdx.x;
    int tid = threadIdx.x;
    int s0 = g_offs[n], s1 = g_offs[n + 1];
    float acc0 = 0.f, acc1 = 0.f;
    float accr0 = 0.f, accr1 = 0.f;
    int j = s0;
    for (; j + 1 < s1; j += 2) {
        int codeA = g_csr[j], codeB = g_csr[j + 1];
        int eA = codeA >> 2, sA = codeA & 3;
        int eB = codeB >> 2, sB = codeB & 3;
        acc0 += g_esum2[(size_t)eA * OUTD + tid];
        acc1 += g_esum2[(size_t)eB * OUTD + tid];
        if (tid < RANK) {
            accr0 += g_tee[((size_t)eA * 4 + sA) * RANK + tid];
            accr1 += g_tee[((size_t)eB * 4 + sB) * RANK + tid];
        }
    }
    if (j < s1) {
        int code = g_csr[j];
        int e = code >> 2, s = code & 3;
        acc0 += g_esum2[(size_t)e * OUTD + tid];
        if (tid < RANK) accr0 += g_tee[((size_t)e * 4 + s) * RANK + tid];
    }
    g_nodeacc[(size_t)n * OUTD + tid] = acc0 + acc1;
    if (tid < RANK) g_accR[(size_t)n * RANK + tid] = tf32r(accr0 + accr1);
}

// ---------------- launch ----------------
extern "C" void kernel_launch(void* const* d_in, const int* in_sizes, int n_in,
                              void* d_out, int out_size)
{
    const float* embedding  = (const float*)d_in[0];
    const float* global_emb = (const float*)d_in[1];
    const float* pW         = (const float*)d_in[2];
    const float* pb         = (const float*)d_in[3];
    const float* qW         = (const float*)d_in[4];
    const float* qb         = (const float*)d_in[5];
    const float* p2W1       = (const float*)d_in[6];
    const float* p2b1       = (const float*)d_in[7];
    const float* p2W2       = (const float*)d_in[8];
    const float* p2b2       = (const float*)d_in[9];
    const float* aW         = (const float*)d_in[10];
    const float* ab         = (const float*)d_in[11];
    const int*   edge_nodes = (const int*)d_in[12];
    const int*   edge_size  = (const int*)d_in[14];
    const int*   node_deg   = (const int*)d_in[15];
    const int*   inc_node   = (const int*)d_in[16];
    const int*   inc_edge   = (const int*)d_in[17];
    const int*   inc_slot   = (const int*)d_in[18];

    const int N    = in_sizes[0] / FEAT;
    const int E    = in_sizes[14];
    const int NINC = in_sizes[16];

    float *p_embR, *p_emb_new, *p_hidden, *p_emb_new2, *p_residual, *p_nodeacc, *p_accR;
    float *p_WtC, *p_Wt2, *p_WtQ, *p_biasC;
    int *p_offs, *p_cursor;
    cudaGetSymbolAddress((void**)&p_embR,     g_embR);
    cudaGetSymbolAddress((void**)&p_emb_new,  g_emb_new);
    cudaGetSymbolAddress((void**)&p_hidden,   g_hidden);
    cudaGetSymbolAddress((void**)&p_emb_new2, g_emb_new2);
    cudaGetSymbolAddress((void**)&p_residual, g_residual);
    cudaGetSymbolAddress((void**)&p_nodeacc,  g_nodeacc);
    cudaGetSymbolAddress((void**)&p_accR,     g_accR);
    cudaGetSymbolAddress((void**)&p_offs,     g_offs);
    cudaGetSymbolAddress((void**)&p_cursor,   g_cursor);
    cudaGetSymbolAddress((void**)&p_WtC,  g_WtC);
    cudaGetSymbolAddress((void**)&p_Wt2,  g_Wt2);
    cudaGetSymbolAddress((void**)&p_WtQ,  g_WtQ);
    cudaGetSymbolAddress((void**)&p_biasC, g_biasC);

    const int SMEM128 = (2 * 128 * 36 + 2 * 128 * 36) * 4;  // 73728
    cudaFuncSetAttribute(mma_gemm<128>, cudaFuncAttributeMaxDynamicSharedMemorySize, SMEM128);

    const int Mtiles = (N + 127) / 128;   // 235
    const int n4 = N * FEAT / 4;

    // 0: mega-prep (transposes + biases + emb round + pad)
    prep_all<<<680 + (n4 + 255) / 256, 256>>>(embedding, p2W1, p2W2, aW, pW, qW,
                                              p2b1, ab, pb, n4);
    // 1: merged G2+G4+G1: [hidden | residual | emb_new] = split(embR @ WtC^T + biasC)
    mma_gemm<128><<<dim3(NC / 128, Mtiles), 256, SMEM128>>>(
        p_embR, p_WtC, p_biasC, p_hidden, p_residual, p_emb_new, N, NC, FEAT, 3,
        nullptr, nullptr, nullptr);
    // 2: G3 emb_new2 = hidden @ p2W2 + p2b2                            [N x 256]
    mma_gemm<128><<<dim3(OUTD / 128, Mtiles), 256, SMEM128>>>(
        p_hidden, p_Wt2, p2b2, p_emb_new2, nullptr, nullptr, N, OUTD, HID, 0,
        nullptr, nullptr, nullptr);
    // 3 (ncu target): edge-level tanh(ee) + relu(esum2)
    edge_kernel<<<(E + 1) / 2, 256>>>(global_emb, edge_nodes, edge_size, node_deg, E);
    // 4: CSR offsets
    scan_offsets<<<1, 1024>>>(node_deg, p_offs, p_cursor, N);
    // 5: CSR fill
    csr_fill<<<(NINC + 255) / 256, 256>>>(inc_node, inc_edge, inc_slot, NINC);
    // 6: node-major gather
    node_gather<<<N, 256>>>();
    // 7: final fused GEMM: out = relu((accR@qW^T + acc256)/deg + qb) + residual
    mma_gemm<128><<<dim3(OUTD / 128, Mtiles), 256, SMEM128>>>(
        p_accR, p_WtQ, qb, (float*)d_out, nullptr, nullptr, N, OUTD, RANK, 2,
        p_nodeacc, p_residual, node_deg);
}

// round 9
// speedup vs baseline: 1.0051x; 1.0051x over previous
#include <cuda_runtime.h>
#include <math.h>
#include <stdint.h>

// Problem constants
#define NN   30000
#define NE   60000
#define FEAT 256
#define HID  1024
#define OUTD 256
#define RANK 64
#define NC   1280   // HID + OUTD (merged G2+G4)

// ---------------- scratch (device globals) ----------------
__device__ float g_embR    [NN * FEAT];
__device__ float g_emb_new [NN * RANK];
__device__ float g_hidden  [NN * HID];    // stored tf32-rounded
__device__ float g_emb_new2[NN * OUTD];
__device__ float g_residual[NN * OUTD];
__device__ float g_tee     [NE * 4 * RANK];
__device__ float g_esum2   [NE * OUTD];
__device__ float g_nodeacc [NN * OUTD];
__device__ float g_accR    [NN * RANK];   // stored tf32-rounded
__device__ int   g_offs    [NN + 1];
__device__ int   g_cursor  [NN];
__device__ int   g_csr     [NE * 4];
// K-major tf32-rounded weights
__device__ float g_WtC [NC * FEAT];       // [Wt1 ; WtA]  1280 x 256
__device__ float g_Wt2 [OUTD * HID];
__device__ float g_WtP [RANK * FEAT];
__device__ float g_WtQ [OUTD * RANK];
__device__ float g_biasC [NC];
__device__ float g_biasP [RANK];

// ---------------- helpers ----------------
__device__ __forceinline__ uint32_t smem_u32(const void* p) {
    uint32_t a;
    asm("{ .reg .u64 t; cvta.to.shared.u64 t, %1; cvt.u32.u64 %0, t; }" : "=r"(a) : "l"(p));
    return a;
}
__device__ __forceinline__ float tf32r(float x) {
    uint32_t u;
    asm("cvt.rna.tf32.f32 %0, %1;" : "=r"(u) : "f"(x));
    return __uint_as_float(u);
}
__device__ __forceinline__ void cp16(uint32_t dst, const void* src, int szbytes) {
    asm volatile("cp.async.ca.shared.global [%0], [%1], 16, %2;"
                 :: "r"(dst), "l"(src), "r"(szbytes) : "memory");
}
#define CP_COMMIT() asm volatile("cp.async.commit_group;" ::: "memory")
#define CP_WAIT(n)  asm volatile("cp.async.wait_group %0;" :: "n"(n) : "memory")

__device__ __forceinline__ void mma16n8k8(float* d, const uint32_t* a, const uint32_t* b) {
    asm volatile(
        "mma.sync.aligned.m16n8k8.row.col.f32.tf32.tf32.f32 "
        "{%0,%1,%2,%3}, {%4,%5,%6,%7}, {%8,%9}, {%0,%1,%2,%3};"
        : "+f"(d[0]), "+f"(d[1]), "+f"(d[2]), "+f"(d[3])
        : "r"(a[0]), "r"(a[1]), "r"(a[2]), "r"(a[3]), "r"(b[0]), "r"(b[1]));
}

// ---------------- mega-prep ----------------
// blocks [0,608): transposes; [608,614): biasC+biasP; [614, 614+n4/256): emb round
__global__ void prep_all(const float* __restrict__ emb,
                         const float* __restrict__ p2W1, const float* __restrict__ p2W2,
                         const float* __restrict__ aW,   const float* __restrict__ pW,
                         const float* __restrict__ qW,
                         const float* __restrict__ p2b1, const float* __restrict__ ab_,
                         const float* __restrict__ pb_,  int n4)
{
    __shared__ float t[32][33];
    const int bx = blockIdx.x;
    const int tid = threadIdx.x;
    if (bx < 608) {
        const float* W; float* Wt; int K, N, t0;
        if      (bx < 256) { W = p2W1; Wt = g_WtC;              K = FEAT; N = HID;  t0 = 0;   }
        else if (bx < 512) { W = p2W2; Wt = g_Wt2;              K = HID;  N = OUTD; t0 = 256; }
        else if (bx < 576) { W = aW;   Wt = g_WtC + HID * FEAT; K = FEAT; N = OUTD; t0 = 512; }
        else if (bx < 592) { W = pW;   Wt = g_WtP;              K = FEAT; N = RANK; t0 = 576; }
        else               { W = qW;   Wt = g_WtQ;              K = RANK; N = OUTD; t0 = 592; }
        int tt = bx - t0;
        int tiles_n = N >> 5;
        int n0 = (tt % tiles_n) * 32, k0 = (tt / tiles_n) * 32;
        int tx = tid & 31, ty = tid >> 5;
        for (int i = ty; i < 32; i += 8)
            t[i][tx] = W[(k0 + i) * N + n0 + tx];
        __syncthreads();
        for (int i = ty; i < 32; i += 8)
            Wt[(n0 + i) * K + k0 + tx] = tf32r(t[tx][i]);
    } else if (bx < 614) {
        int i = (bx - 608) * 256 + tid;
        if      (i < HID)       g_biasC[i] = p2b1[i] + p2W1[FEAT * HID + i];
        else if (i < HID + OUTD) g_biasC[i] = ab_[i - HID] + aW[FEAT * OUTD + (i - HID)];
        else if (i < HID + OUTD + RANK) g_biasP[i - HID - OUTD] = pb_[i - HID - OUTD] + pW[FEAT * RANK + (i - HID - OUTD)];
    } else {
        int i = (bx - 614) * 256 + tid;
        if (i < n4) {
            float4 v = ((const float4*)emb)[i];
            v.x = tf32r(v.x); v.y = tf32r(v.y); v.z = tf32r(v.z); v.w = tf32r(v.w);
            ((float4*)g_embR)[i] = v;
        }
    }
}

// ---------------- CSR offsets: two-pass coarsened scan ----------------
__global__ __launch_bounds__(1024)
void scan_offsets(const int* __restrict__ deg, int* __restrict__ offs,
                  int* __restrict__ cursor, int N)
{
    constexpr int CE = 32;
    const int tid = threadIdx.x;
    const int start = tid * CE;

    int local = 0;
    if (start < N) {
        #pragma unroll
        for (int j = 0; j < CE; j += 4) {
            int i = start + j;
            if (i + 3 < N) {
                int4 v = *(const int4*)(deg + i);
                local += v.x + v.y + v.z + v.w;
            } else {
                #pragma unroll
                for (int k = 0; k < 4; k++) if (i + k < N) local += deg[i + k];
            }
        }
    }
    __shared__ int warpsum[32];
    int lane = tid & 31, w = tid >> 5;
    int x = local;
    #pragma unroll
    for (int o = 1; o < 32; o <<= 1) { int y = __shfl_up_sync(~0u, x, o); if (lane >= o) x += y; }
    if (lane == 31) warpsum[w] = x;
    __syncthreads();
    if (w == 0) {
        int s = warpsum[lane];
        #pragma unroll
        for (int o = 1; o < 32; o <<= 1) { int y = __shfl_up_sync(~0u, s, o); if (lane >= o) s += y; }
        warpsum[lane] = s;
    }
    __syncthreads();
    int base = x - local + (w > 0 ? warpsum[w - 1] : 0);

    if (start < N) {
        int run = base;
        #pragma unroll
        for (int j = 0; j < CE; j++) {
            int i = start + j;
            if (i < N) { offs[i] = run; cursor[i] = 0; run += deg[i]; }
        }
        if (tid == (N - 1) / CE) offs[N] = run;
    }
}

__global__ void csr_fill(const int* __restrict__ inc_node, const int* __restrict__ inc_edge,
                         const int* __restrict__ inc_slot, int NINC)
{
    int i = blockIdx.x * blockDim.x + threadIdx.x;
    if (i < NINC) {
        int n = inc_node[i];
        int p = atomicAdd(&g_cursor[n], 1);
        g_csr[g_offs[n] + p] = (inc_edge[i] << 2) | inc_slot[i];
    }
}

// ---------------- tensor-core tf32 GEMM ----------------
// mode 0: C = acc + bias
// mode 2: C = relu((acc + addSrc)/deg + bias) + resid
// mode 3: split: col<1024 -> relu,tf32r -> C (stride HID); else relu -> C2 (stride OUTD)
template<int NT>
__global__ __launch_bounds__(256, 2)
void mma_gemm(const float* __restrict__ A, const float* __restrict__ Bt,
              const float* __restrict__ bias,
              float* __restrict__ C, float* __restrict__ C2,
              int M, int N, int K, int mode,
              const float* __restrict__ addSrc, const float* __restrict__ resid,
              const int* __restrict__ degv)
{
    constexpr int ST = 36;
    constexpr int NTILES = NT / 16;
    extern __shared__ float dyn[];
    float* Asm = dyn;
    float* Bsm = dyn + 2 * 128 * ST;

    const int tid  = threadIdx.x;
    const int wid  = tid >> 5;
    const int lane = tid & 31;
    const int grp  = lane >> 2;
    const int tig  = lane & 3;
    const int warpM = (wid & 3) * 32;
    const int warpN = (wid >> 2) * (NT / 2);
    const int rowBase = blockIdx.y * 128;
    const int colBase = blockIdx.x * NT;

    float acc[2][NTILES][4];
    #pragma unroll
    for (int mt = 0; mt < 2; mt++)
        #pragma unroll
        for (int nt = 0; nt < NTILES; nt++)
            #pragma unroll
            for (int i = 0; i < 4; i++) acc[mt][nt][i] = 0.f;

    const uint32_t asm_base = smem_u32(Asm);
    const uint32_t bsm_base = smem_u32(Bsm);

    auto loadChunk = [&](int c, int buf) {
        #pragma unroll
        for (int i = 0; i < 4; i++) {
            int idx = tid + (i << 8);
            int r = idx >> 3, f4 = idx & 7;
            int gr = rowBase + r;
            const float* src = A + (size_t)gr * K + (c << 5) + (f4 << 2);
            uint32_t dst = asm_base + (buf * 128 * ST + r * ST + (f4 << 2)) * 4;
            cp16(dst, src, gr < M ? 16 : 0);
        }
        #pragma unroll
        for (int i = 0; i < NT / 32; i++) {
            int idx = tid + (i << 8);
            int r = idx >> 3, f4 = idx & 7;
            const float* src = Bt + (size_t)(colBase + r) * K + (c << 5) + (f4 << 2);
            uint32_t dst = bsm_base + (buf * NT * ST + r * ST + (f4 << 2)) * 4;
            cp16(dst, src, 16);
        }
        CP_COMMIT();
    };

    const int nch = K >> 5;
    loadChunk(0, 0);

    for (int c = 0; c < nch; ++c) {
        const int buf = c & 1;
        if (c + 1 < nch) { loadChunk(c + 1, buf ^ 1); CP_WAIT(1); }
        else             { CP_WAIT(0); }
        __syncthreads();

        const float* ab = Asm + buf * 128 * ST;
        const float* bb = Bsm + buf * NT * ST;
        #pragma unroll
        for (int ks = 0; ks < 4; ++ks) {
            const int kb = ks << 3;
            uint32_t afr[2][4];
            #pragma unroll
            for (int mt = 0; mt < 2; mt++) {
                int base = (warpM + mt * 16 + grp) * ST + kb + tig;
                afr[mt][0] = __float_as_uint(ab[base]);
                afr[mt][1] = __float_as_uint(ab[base + 8 * ST]);
                afr[mt][2] = __float_as_uint(ab[base + 4]);
                afr[mt][3] = __float_as_uint(ab[base + 8 * ST + 4]);
            }
            uint32_t bfr[NTILES][2];
            #pragma unroll
            for (int nt = 0; nt < NTILES; nt++) {
                int base = (warpN + nt * 8 + grp) * ST + kb + tig;
                bfr[nt][0] = __float_as_uint(bb[base]);
                bfr[nt][1] = __float_as_uint(bb[base + 4]);
            }
            #pragma unroll
            for (int mt = 0; mt < 2; mt++)
                #pragma unroll
                for (int nt = 0; nt < NTILES; nt++)
                    mma16n8k8(acc[mt][nt], afr[mt], bfr[nt]);
        }
        __syncthreads();
    }

    #pragma unroll
    for (int mt = 0; mt < 2; mt++) {
        #pragma unroll
        for (int nt = 0; nt < NTILES; nt++) {
            int col = colBase + warpN + nt * 8 + (tig << 1);
            float b0 = bias[col], b1 = bias[col + 1];
            #pragma unroll
            for (int h = 0; h < 2; h++) {
                int row = rowBase + warpM + mt * 16 + grp + h * 8;
                if (row >= M) continue;
                float v0 = acc[mt][nt][2 * h];
                float v1 = acc[mt][nt][2 * h + 1];
                if (mode == 3) {
                    v0 = fmaxf(v0 + b0, 0.f); v1 = fmaxf(v1 + b1, 0.f);
                    if (col < HID) {
                        *(float2*)(C + (size_t)row * HID + col) =
                            make_float2(tf32r(v0), tf32r(v1));
                    } else {
                        *(float2*)(C2 + (size_t)row * OUTD + (col - HID)) = make_float2(v0, v1);
                    }
                } else if (mode == 2) {
                    float rd = 1.0f / (float)degv[row];
                    size_t base = (size_t)row * N + col;
                    v0 = fmaxf((v0 + addSrc[base])     * rd + b0, 0.f) + resid[base];
                    v1 = fmaxf((v1 + addSrc[base + 1]) * rd + b1, 0.f) + resid[base + 1];
                    *(float2*)(C + base) = make_float2(v0, v1);
                } else {
                    *(float2*)(C + (size_t)row * N + col) = make_float2(v0 + b0, v1 + b1);
                }
            }
        }
    }
}

// ---------------- edge kernel: 2 edges per block, 32-bit addressing ----------------
__global__ __launch_bounds__(256)
void edge_kernel(const float* __restrict__ global_emb,
                 const int* __restrict__ edge_nodes,
                 const int* __restrict__ edge_size,
                 const int* __restrict__ node_degree,
                 int E)
{
    __shared__ int   s_nodes[2][4];
    __shared__ float s_scale[2][4];
    __shared__ int   s_size[2];

    const int half = threadIdx.x >> 7;
    const int lt   = threadIdx.x & 127;
    const int e    = blockIdx.x * 2 + half;
    const bool active = (e < E);

    if (active && lt < 4) {
        int sz = edge_size[e];
        if (lt == 0) s_size[half] = sz;
        int n = edge_nodes[e * 4 + lt];
        s_nodes[half][lt] = n;
        float a = (sz == 1) ? 1.0f : (sz <= 3 ? (1.0f / 3.0f) : 0.25f);
        s_scale[half][lt] = __powf((float)node_degree[n], a);
    }
    __syncthreads();
    if (!active) return;

    const int sz = s_size[half];
    const int k = 4 - sz;
    const float invf = (sz == 3) ? 0.5f : (sz == 4 ? (1.0f / 6.0f) : 1.0f);

    if (lt < RANK) {
        const int r = lt;
        float g = global_emb[r];
        float gf = (k == 0) ? 1.0f : (k == 1 ? g : g * g);
        float t[4];
        #pragma unroll
        for (int s = 0; s < 4; s++)
            t[s] = (s < sz) ? s_scale[half][s] * g_emb_new[s_nodes[half][s] * RANK + r] : 1.0f;
        float loo[4];
        loo[0] = t[1] * t[2] * t[3];
        loo[1] = t[0] * t[2] * t[3];
        loo[2] = t[0] * t[1] * t[3];
        loo[3] = t[0] * t[1] * t[2];
        float f = gf * invf;
        unsigned tb = (unsigned)e * (4u * RANK) + r;
        for (int s = 0; s < sz; s++)
            g_tee[tb + (unsigned)s * RANK] = tanhf(loo[s] * f);
    }

    {
        float sum0 = 0.f, sum1 = 0.f;
        for (int s = 0; s < sz; s++) {
            const float* row = g_emb_new2 + (unsigned)s_nodes[half][s] * OUTD;
            sum0 += row[lt];
            sum1 += row[lt + 128];
        }
        unsigned eb = (unsigned)e * OUTD + lt;
        g_esum2[eb]       = fmaxf(sum0, 0.f);
        g_esum2[eb + 128] = fmaxf(sum1, 0.f);
    }
}

// ---------------- node-major gather (unrolled x2, 32-bit addressing) ----------------
__global__ __launch_bounds__(256)
void node_gather()
{
    int n = blockIdx.x;
    int tid = threadIdx.x;
    int s0 = g_offs[n], s1 = g_offs[n + 1];
    float acc0 = 0.f, acc1 = 0.f;
    float accr0 = 0.f, accr1 = 0.f;
    int j = s0;
    for (; j + 1 < s1; j += 2) {
        int codeA = g_csr[j], codeB = g_csr[j + 1];
        unsigned offA = (unsigned)(codeA >> 2) * OUTD;
        unsigned offB = (unsigned)(codeB >> 2) * OUTD;
        acc0 += g_esum2[offA + tid];
        acc1 += g_esum2[offB + tid];
        if (tid < RANK) {
            accr0 += g_tee[(unsigned)codeA * RANK + tid];   // code = e*4 + s
            accr1 += g_tee[(unsigned)codeB * RANK + tid];
        }
    }
    if (j < s1) {
        int code = g_csr[j];
        acc0 += g_esum2[(unsigned)(code >> 2) * OUTD + tid];
        if (tid < RANK) accr0 += g_tee[(unsigned)code * RANK + tid];
    }
    g_nodeacc[(unsigned)n * OUTD + tid] = acc0 + acc1;
    if (tid < RANK) g_accR[(unsigned)n * RANK + tid] = tf32r(accr0 + accr1);
}

// ---------------- launch ----------------
extern "C" void kernel_launch(void* const* d_in, const int* in_sizes, int n_in,
                              void* d_out, int out_size)
{
    const float* embedding  = (const float*)d_in[0];
    const float* global_emb = (const float*)d_in[1];
    const float* pW         = (const float*)d_in[2];
    const float* pb         = (const float*)d_in[3];
    const float* qW         = (const float*)d_in[4];
    const float* qb         = (const float*)d_in[5];
    const float* p2W1       = (const float*)d_in[6];
    const float* p2b1       = (const float*)d_in[7];
    const float* p2W2       = (const float*)d_in[8];
    const float* p2b2       = (const float*)d_in[9];
    const float* aW         = (const float*)d_in[10];
    const float* ab         = (const float*)d_in[11];
    const int*   edge_nodes = (const int*)d_in[12];
    const int*   edge_size  = (const int*)d_in[14];
    const int*   node_deg   = (const int*)d_in[15];
    const int*   inc_node   = (const int*)d_in[16];
    const int*   inc_edge   = (const int*)d_in[17];
    const int*   inc_slot   = (const int*)d_in[18];

    const int N    = in_sizes[0] / FEAT;
    const int E    = in_sizes[14];
    const int NINC = in_sizes[16];

    float *p_embR, *p_emb_new, *p_hidden, *p_emb_new2, *p_residual, *p_nodeacc, *p_accR;
    float *p_WtC, *p_Wt2, *p_WtP, *p_WtQ, *p_biasC, *p_biasP;
    int *p_offs, *p_cursor;
    cudaGetSymbolAddress((void**)&p_embR,     g_embR);
    cudaGetSymbolAddress((void**)&p_emb_new,  g_emb_new);
    cudaGetSymbolAddress((void**)&p_hidden,   g_hidden);
    cudaGetSymbolAddress((void**)&p_emb_new2, g_emb_new2);
    cudaGetSymbolAddress((void**)&p_residual, g_residual);
    cudaGetSymbolAddress((void**)&p_nodeacc,  g_nodeacc);
    cudaGetSymbolAddress((void**)&p_accR,     g_accR);
    cudaGetSymbolAddress((void**)&p_offs,     g_offs);
    cudaGetSymbolAddress((void**)&p_cursor,   g_cursor);
    cudaGetSymbolAddress((void**)&p_WtC,  g_WtC);
    cudaGetSymbolAddress((void**)&p_Wt2,  g_Wt2);
    cudaGetSymbolAddress((void**)&p_WtP,  g_WtP);
    cudaGetSymbolAddress((void**)&p_WtQ,  g_WtQ);
    cudaGetSymbolAddress((void**)&p_biasC, g_biasC);
    cudaGetSymbolAddress((void**)&p_biasP, g_biasP);

    const int SMEM128 = (2 * 128 * 36 + 2 * 128 * 36) * 4;  // 73728
    const int SMEM64  = (2 * 128 * 36 + 2 * 64  * 36) * 4;  // 55296
    cudaFuncSetAttribute(mma_gemm<128>, cudaFuncAttributeMaxDynamicSharedMemorySize, SMEM128);
    cudaFuncSetAttribute(mma_gemm<64>,  cudaFuncAttributeMaxDynamicSharedMemorySize, SMEM64);

    const int Mtiles = (N + 127) / 128;   // 235
    const int n4 = N * FEAT / 4;

    // 0: CSR offsets
    scan_offsets<<<1, 1024>>>(node_deg, p_offs, p_cursor, N);
    // 1: CSR fill
    csr_fill<<<(NINC + 255) / 256, 256>>>(inc_node, inc_edge, inc_slot, NINC);
    // 2: mega-prep (transposes + biases + emb round)
    prep_all<<<614 + (n4 + 255) / 256, 256>>>(embedding, p2W1, p2W2, aW, pW, qW,
                                              p2b1, ab, pb, n4);
    // 3 (ncu target): merged G2+G4: [hidden | residual] = relu(embR @ WtC^T + biasC)
    mma_gemm<128><<<dim3(NC / 128, Mtiles), 256, SMEM128>>>(
        p_embR, p_WtC, p_biasC, p_hidden, p_residual, N, NC, FEAT, 3,
        nullptr, nullptr, nullptr);
    // 4: G1 emb_new = embR @ pW^T + biasP                              [N x 64]
    mma_gemm<64><<<dim3(1, Mtiles), 256, SMEM64>>>(
        p_embR, p_WtP, p_biasP, p_emb_new, nullptr, N, RANK, FEAT, 0,
        nullptr, nullptr, nullptr);
    // 5: G3 emb_new2 = hidden @ p2W2 + p2b2                            [N x 256]
    mma_gemm<128><<<dim3(OUTD / 128, Mtiles), 256, SMEM128>>>(
        p_hidden, p_Wt2, p2b2, p_emb_new2, nullptr, N, OUTD, HID, 0,
        nullptr, nullptr, nullptr);
    // 6: edge-level tanh(ee) + relu(esum2)
    edge_kernel<<<(E + 1) / 2, 256>>>(global_emb, edge_nodes, edge_size, node_deg, E);
    // 7: node-major gather
    node_gather<<<N, 256>>>();
    // 8: final fused GEMM: out = relu((accR@qW^T + acc256)/deg + qb) + residual
    mma_gemm<128><<<dim3(OUTD / 128, Mtiles), 256, SMEM128>>>(
        p_accR, p_WtQ, qb, (float*)d_out, nullptr, N, OUTD, RANK, 2,
        p_nodeacc, p_residual, node_deg);
}

// round 11
// speedup vs baseline: 1.2169x; 1.2107x over previous
#include <cuda_runtime.h>
#include <cuda_fp16.h>
#include <math.h>
#include <stdint.h>

// Problem constants
#define NN   30000
#define NE   60000
#define FEAT 256
#define HID  1024
#define OUTD 256
#define RANK 64
#define NC   1280   // HID + OUTD (merged G2+G4)

// ---------------- scratch (device globals) ----------------
__device__ __half g_embH   [NN * FEAT];     // fp16 embedding
__device__ float  g_emb_new[NN * RANK];     // fp32 (edge kernel input)
__device__ __half g_hidden [NN * HID];      // fp16 hidden
__device__ float  g_emb_new2[NN * OUTD];
__device__ float  g_residual[NN * OUTD];
__device__ float  g_tee     [NE * 4 * RANK];
__device__ float  g_esum2   [NE * OUTD];
__device__ float  g_nodeacc [NN * OUTD];
__device__ __half g_accRh   [NN * RANK];    // fp16 accR
__device__ int    g_offs    [NN + 1];
__device__ int    g_cursor  [NN];
__device__ int    g_csr     [NE * 4];
// K-major fp16 weights
__device__ __half g_WtC [NC * FEAT];        // [Wt1 ; WtA]
__device__ __half g_Wt2 [OUTD * HID];
__device__ __half g_WtP [RANK * FEAT];
__device__ __half g_WtQ [OUTD * RANK];
__device__ float  g_biasC [NC];
__device__ float  g_biasP [RANK];

// ---------------- helpers ----------------
__device__ __forceinline__ uint32_t smem_u32(const void* p) {
    uint32_t a;
    asm("{ .reg .u64 t; cvta.to.shared.u64 t, %1; cvt.u32.u64 %0, t; }" : "=r"(a) : "l"(p));
    return a;
}
__device__ __forceinline__ uint32_t h2_as_u32(__half2 h) {
    uint32_t u;
    memcpy(&u, &h, 4);
    return u;
}
__device__ __forceinline__ void cp16(uint32_t dst, const void* src, int szbytes) {
    asm volatile("cp.async.ca.shared.global [%0], [%1], 16, %2;"
                 :: "r"(dst), "l"(src), "r"(szbytes) : "memory");
}
#define CP_COMMIT() asm volatile("cp.async.commit_group;" ::: "memory")
#define CP_WAIT(n)  asm volatile("cp.async.wait_group %0;" :: "n"(n) : "memory")

// fp16 tensor-core mma: D(f32) += A(f16) * B(f16)
__device__ __forceinline__ void mma16n8k16(float* d, const uint32_t* a, const uint32_t* b) {
    asm volatile(
        "mma.sync.aligned.m16n8k16.row.col.f32.f16.f16.f32 "
        "{%0,%1,%2,%3}, {%4,%5,%6,%7}, {%8,%9}, {%0,%1,%2,%3};"
        : "+f"(d[0]), "+f"(d[1]), "+f"(d[2]), "+f"(d[3])
        : "r"(a[0]), "r"(a[1]), "r"(a[2]), "r"(a[3]), "r"(b[0]), "r"(b[1]));
}

// ---------------- mega-prep ----------------
// blocks [0,608): transposes fp32->fp16; [608,614): biasC+biasP; [614, ...): emb fp16
__global__ void prep_all(const float* __restrict__ emb,
                         const float* __restrict__ p2W1, const float* __restrict__ p2W2,
                         const float* __restrict__ aW,   const float* __restrict__ pW,
                         const float* __restrict__ qW,
                         const float* __restrict__ p2b1, const float* __restrict__ ab_,
                         const float* __restrict__ pb_,  int n4)
{
    __shared__ float t[32][33];
    const int bx = blockIdx.x;
    const int tid = threadIdx.x;
    if (bx < 608) {
        const float* W; __half* Wt; int K, N, t0;
        if      (bx < 256) { W = p2W1; Wt = g_WtC;              K = FEAT; N = HID;  t0 = 0;   }
        else if (bx < 512) { W = p2W2; Wt = g_Wt2;              K = HID;  N = OUTD; t0 = 256; }
        else if (bx < 576) { W = aW;   Wt = g_WtC + HID * FEAT; K = FEAT; N = OUTD; t0 = 512; }
        else if (bx < 592) { W = pW;   Wt = g_WtP;              K = FEAT; N = RANK; t0 = 576; }
        else               { W = qW;   Wt = g_WtQ;              K = RANK; N = OUTD; t0 = 592; }
        int tt = bx - t0;
        int tiles_n = N >> 5;
        int n0 = (tt % tiles_n) * 32, k0 = (tt / tiles_n) * 32;
        int tx = tid & 31, ty = tid >> 5;
        for (int i = ty; i < 32; i += 8)
            t[i][tx] = W[(k0 + i) * N + n0 + tx];
        __syncthreads();
        for (int i = ty; i < 32; i += 8)
            Wt[(n0 + i) * K + k0 + tx] = __float2half_rn(t[tx][i]);
    } else if (bx < 614) {
        int i = (bx - 608) * 256 + tid;
        if      (i < HID)        g_biasC[i] = p2b1[i] + p2W1[FEAT * HID + i];
        else if (i < HID + OUTD) g_biasC[i] = ab_[i - HID] + aW[FEAT * OUTD + (i - HID)];
        else if (i < HID + OUTD + RANK) g_biasP[i - HID - OUTD] = pb_[i - HID - OUTD] + pW[FEAT * RANK + (i - HID - OUTD)];
    } else {
        int i = (bx - 614) * 256 + tid;
        if (i < n4) {
            float4 v = ((const float4*)emb)[i];
            uint2 o;
            o.x = h2_as_u32(__floats2half2_rn(v.x, v.y));
            o.y = h2_as_u32(__floats2half2_rn(v.z, v.w));
            ((uint2*)g_embH)[i] = o;
        }
    }
}

// ---------------- CSR offsets ----------------
__global__ __launch_bounds__(1024)
void scan_offsets(const int* __restrict__ deg, int* __restrict__ offs,
                  int* __restrict__ cursor, int N)
{
    constexpr int CE = 32;
    const int tid = threadIdx.x;
    const int start = tid * CE;

    int local = 0;
    if (start < N) {
        #pragma unroll
        for (int j = 0; j < CE; j += 4) {
            int i = start + j;
            if (i + 3 < N) {
                int4 v = *(const int4*)(deg + i);
                local += v.x + v.y + v.z + v.w;
            } else {
                #pragma unroll
                for (int k = 0; k < 4; k++) if (i + k < N) local += deg[i + k];
            }
        }
    }
    __shared__ int warpsum[32];
    int lane = tid & 31, w = tid >> 5;
    int x = local;
    #pragma unroll
    for (int o = 1; o < 32; o <<= 1) { int y = __shfl_up_sync(~0u, x, o); if (lane >= o) x += y; }
    if (lane == 31) warpsum[w] = x;
    __syncthreads();
    if (w == 0) {
        int s = warpsum[lane];
        #pragma unroll
        for (int o = 1; o < 32; o <<= 1) { int y = __shfl_up_sync(~0u, s, o); if (lane >= o) s += y; }
        warpsum[lane] = s;
    }
    __syncthreads();
    int base = x - local + (w > 0 ? warpsum[w - 1] : 0);

    if (start < N) {
        int run = base;
        #pragma unroll
        for (int j = 0; j < CE; j++) {
            int i = start + j;
            if (i < N) { offs[i] = run; cursor[i] = 0; run += deg[i]; }
        }
        if (tid == (N - 1) / CE) offs[N] = run;
    }
}

__global__ void csr_fill(const int* __restrict__ inc_node, const int* __restrict__ inc_edge,
                         const int* __restrict__ inc_slot, int NINC)
{
    int i = blockIdx.x * blockDim.x + threadIdx.x;
    if (i < NINC) {
        int n = inc_node[i];
        int p = atomicAdd(&g_cursor[n], 1);
        g_csr[g_offs[n] + p] = (inc_edge[i] << 2) | inc_slot[i];
    }
}

// ---------------- fp16 tensor-core GEMM (m16n8k16) ----------------
// A[M,K] fp16 row-major, Bt[N,K] fp16 K-major; fp32 accumulate.
// CTA tile 128 x NT; 8 warps 4(M)x2(N); warp 32 x NT/2; K-chunk 32.
// mode 0: C(f32) = acc + bias
// mode 2: C(f32) = relu((acc + addSrc)/deg + bias) + resid
// mode 3: col<HID -> relu -> half2 into Chid; else relu -> f32 C2 (stride OUTD)
template<int NT>
__global__ __launch_bounds__(256, 2)
void mma_gemm(const __half* __restrict__ A, const __half* __restrict__ Bt,
              const float* __restrict__ bias,
              float* __restrict__ C, float* __restrict__ C2,
              int M, int N, int K, int mode,
              const float* __restrict__ addSrc, const float* __restrict__ resid,
              const int* __restrict__ degv)
{
    constexpr int STW = 20;                // words per row (40 halves: 32 + 8 pad)
    constexpr int NTILES = NT / 16;
    extern __shared__ uint32_t dyn32[];
    uint32_t* Asm = dyn32;                 // 2 bufs x 128 x STW words
    uint32_t* Bsm = dyn32 + 2 * 128 * STW; // 2 bufs x NT x STW words

    const int tid  = threadIdx.x;
    const int wid  = tid >> 5;
    const int lane = tid & 31;
    const int grp  = lane >> 2;
    const int tig  = lane & 3;
    const int warpM = (wid & 3) * 32;
    const int warpN = (wid >> 2) * (NT / 2);
    const int rowBase = blockIdx.y * 128;
    const int colBase = blockIdx.x * NT;

    float acc[2][NTILES][4];
    #pragma unroll
    for (int mt = 0; mt < 2; mt++)
        #pragma unroll
        for (int nt = 0; nt < NTILES; nt++)
            #pragma unroll
            for (int i = 0; i < 4; i++) acc[mt][nt][i] = 0.f;

    const uint32_t asm_base = smem_u32(Asm);
    const uint32_t bsm_base = smem_u32(Bsm);

    auto loadChunk = [&](int c, int buf) {
        // A: 128 rows x 32 halves (64B) = 512 x 16B segs; 2 per thread
        #pragma unroll
        for (int i = 0; i < 2; i++) {
            int idx = tid + (i << 8);
            int r = idx >> 2, seg = idx & 3;
            int gr = rowBase + r;
            const __half* src = A + (size_t)gr * K + (c << 5) + (seg << 3);
            uint32_t dst = asm_base + (buf * 128 * STW + r * STW + (seg << 2)) * 4;
            cp16(dst, src, gr < M ? 16 : 0);
        }
        // B: NT rows x 32 halves
        #pragma unroll
        for (int i = 0; i < NT / 64; i++) {
            int idx = tid + (i << 8);
            int r = idx >> 2, seg = idx & 3;
            const __half* src = Bt + (size_t)(colBase + r) * K + (c << 5) + (seg << 3);
            uint32_t dst = bsm_base + (buf * NT * STW + r * STW + (seg << 2)) * 4;
            cp16(dst, src, 16);
        }
        CP_COMMIT();
    };

    const int nch = K >> 5;
    loadChunk(0, 0);

    for (int c = 0; c < nch; ++c) {
        const int buf = c & 1;
        if (c + 1 < nch) { loadChunk(c + 1, buf ^ 1); CP_WAIT(1); }
        else             { CP_WAIT(0); }
        __syncthreads();

        const uint32_t* ab = Asm + buf * 128 * STW;
        const uint32_t* bb = Bsm + buf * NT * STW;
        #pragma unroll
        for (int ks = 0; ks < 2; ++ks) {          // two k16 steps per 32-half chunk
            const int kw = ks << 3;               // word offset (16 halves)
            uint32_t afr[2][4];
            #pragma unroll
            for (int mt = 0; mt < 2; mt++) {
                int base = (warpM + mt * 16 + grp) * STW + kw + tig;
                afr[mt][0] = ab[base];                // (row grp,    k 2t..2t+1)
                afr[mt][1] = ab[base + 8 * STW];      // (row grp+8,  k 2t..2t+1)
                afr[mt][2] = ab[base + 4];            // (row grp,    k 2t+8..)
                afr[mt][3] = ab[base + 8 * STW + 4];  // (row grp+8,  k 2t+8..)
            }
            uint32_t bfr[NTILES][2];
            #pragma unroll
            for (int nt = 0; nt < NTILES; nt++) {
                int base = (warpN + nt * 8 + grp) * STW + kw + tig;
                bfr[nt][0] = bb[base];
                bfr[nt][1] = bb[base + 4];
            }
            #pragma unroll
            for (int mt = 0; mt < 2; mt++)
                #pragma unroll
                for (int nt = 0; nt < NTILES; nt++)
                    mma16n8k16(acc[mt][nt], afr[mt], bfr[nt]);
        }
        __syncthreads();
    }

    #pragma unroll
    for (int mt = 0; mt < 2; mt++) {
        #pragma unroll
        for (int nt = 0; nt < NTILES; nt++) {
            int col = colBase + warpN + nt * 8 + (tig << 1);
            float b0 = bias[col], b1 = bias[col + 1];
            #pragma unroll
            for (int h = 0; h < 2; h++) {
                int row = rowBase + warpM + mt * 16 + grp + h * 8;
                if (row >= M) continue;
                float v0 = acc[mt][nt][2 * h];
                float v1 = acc[mt][nt][2 * h + 1];
                if (mode == 3) {
                    v0 = fmaxf(v0 + b0, 0.f); v1 = fmaxf(v1 + b1, 0.f);
                    if (col < HID) {
                        __half2 hv = __floats2half2_rn(v0, v1);
                        ((uint32_t*)C)[(size_t)row * (HID / 2) + (col >> 1)] = h2_as_u32(hv);
                    } else {
                        *(float2*)(C2 + (size_t)row * OUTD + (col - HID)) = make_float2(v0, v1);
                    }
                } else if (mode == 2) {
                    float rd = 1.0f / (float)degv[row];
                    size_t base = (size_t)row * N + col;
                    v0 = fmaxf((v0 + addSrc[base])     * rd + b0, 0.f) + resid[base];
                    v1 = fmaxf((v1 + addSrc[base + 1]) * rd + b1, 0.f) + resid[base + 1];
                    *(float2*)(C + base) = make_float2(v0, v1);
                } else {
                    *(float2*)(C + (size_t)row * N + col) = make_float2(v0 + b0, v1 + b1);
                }
            }
        }
    }
}

// ---------------- edge kernel: 2 edges per block ----------------
__global__ __launch_bounds__(256)
void edge_kernel(const float* __restrict__ global_emb,
                 const int* __restrict__ edge_nodes,
                 const int* __restrict__ edge_size,
                 const int* __restrict__ node_degree,
                 int E)
{
    __shared__ int   s_nodes[2][4];
    __shared__ float s_scale[2][4];
    __shared__ int   s_size[2];

    const int half = threadIdx.x >> 7;
    const int lt   = threadIdx.x & 127;
    const int e    = blockIdx.x * 2 + half;
    const bool active = (e < E);

    if (active && lt < 4) {
        int sz = edge_size[e];
        if (lt == 0) s_size[half] = sz;
        int n = edge_nodes[e * 4 + lt];
        s_nodes[half][lt] = n;
        float a = (sz == 1) ? 1.0f : (sz <= 3 ? (1.0f / 3.0f) : 0.25f);
        s_scale[half][lt] = __powf((float)node_degree[n], a);
    }
    __syncthreads();
    if (!active) return;

    const int sz = s_size[half];
    const int k = 4 - sz;
    const float invf = (sz == 3) ? 0.5f : (sz == 4 ? (1.0f / 6.0f) : 1.0f);

    if (lt < RANK) {
        const int r = lt;
        float g = global_emb[r];
        float gf = (k == 0) ? 1.0f : (k == 1 ? g : g * g);
        float t[4];
        #pragma unroll
        for (int s = 0; s < 4; s++)
            t[s] = (s < sz) ? s_scale[half][s] * g_emb_new[s_nodes[half][s] * RANK + r] : 1.0f;
        float loo[4];
        loo[0] = t[1] * t[2] * t[3];
        loo[1] = t[0] * t[2] * t[3];
        loo[2] = t[0] * t[1] * t[3];
        loo[3] = t[0] * t[1] * t[2];
        float f = gf * invf;
        unsigned tb = (unsigned)e * (4u * RANK) + r;
        for (int s = 0; s < sz; s++)
            g_tee[tb + (unsigned)s * RANK] = tanhf(loo[s] * f);
    }

    {
        float sum0 = 0.f, sum1 = 0.f;
        for (int s = 0; s < sz; s++) {
            const float* row = g_emb_new2 + (unsigned)s_nodes[half][s] * OUTD;
            sum0 += row[lt];
            sum1 += row[lt + 128];
        }
        unsigned eb = (unsigned)e * OUTD + lt;
        g_esum2[eb]       = fmaxf(sum0, 0.f);
        g_esum2[eb + 128] = fmaxf(sum1, 0.f);
    }
}

// ---------------- node-major gather ----------------
__global__ __launch_bounds__(256)
void node_gather()
{
    int n = blockIdx.x;
    int tid = threadIdx.x;
    int s0 = g_offs[n], s1 = g_offs[n + 1];
    float acc0 = 0.f, acc1 = 0.f;
    float accr0 = 0.f, accr1 = 0.f;
    int j = s0;
    for (; j + 1 < s1; j += 2) {
        int codeA = g_csr[j], codeB = g_csr[j + 1];
        unsigned offA = (unsigned)(codeA >> 2) * OUTD;
        unsigned offB = (unsigned)(codeB >> 2) * OUTD;
        acc0 += g_esum2[offA + tid];
        acc1 += g_esum2[offB + tid];
        if (tid < RANK) {
            accr0 += g_tee[(unsigned)codeA * RANK + tid];
            accr1 += g_tee[(unsigned)codeB * RANK + tid];
        }
    }
    if (j < s1) {
        int code = g_csr[j];
        acc0 += g_esum2[(unsigned)(code >> 2) * OUTD + tid];
        if (tid < RANK) accr0 += g_tee[(unsigned)code * RANK + tid];
    }
    g_nodeacc[(unsigned)n * OUTD + tid] = acc0 + acc1;
    if (tid < RANK) g_accRh[(unsigned)n * RANK + tid] = __float2half_rn(accr0 + accr1);
}

// ---------------- launch ----------------
extern "C" void kernel_launch(void* const* d_in, const int* in_sizes, int n_in,
                              void* d_out, int out_size)
{
    const float* embedding  = (const float*)d_in[0];
    const float* global_emb = (const float*)d_in[1];
    const float* pW         = (const float*)d_in[2];
    const float* pb         = (const float*)d_in[3];
    const float* qW         = (const float*)d_in[4];
    const float* qb         = (const float*)d_in[5];
    const float* p2W1       = (const float*)d_in[6];
    const float* p2b1       = (const float*)d_in[7];
    const float* p2W2       = (const float*)d_in[8];
    const float* p2b2       = (const float*)d_in[9];
    const float* aW         = (const float*)d_in[10];
    const float* ab         = (const float*)d_in[11];
    const int*   edge_nodes = (const int*)d_in[12];
    const int*   edge_size  = (const int*)d_in[14];
    const int*   node_deg   = (const int*)d_in[15];
    const int*   inc_node   = (const int*)d_in[16];
    const int*   inc_edge   = (const int*)d_in[17];
    const int*   inc_slot   = (const int*)d_in[18];

    const int N    = in_sizes[0] / FEAT;
    const int E    = in_sizes[14];
    const int NINC = in_sizes[16];

    __half *p_embH, *p_hidden, *p_accRh, *p_WtC, *p_Wt2, *p_WtP, *p_WtQ;
    float *p_emb_new, *p_emb_new2, *p_residual, *p_nodeacc, *p_biasC, *p_biasP;
    int *p_offs, *p_cursor;
    cudaGetSymbolAddress((void**)&p_embH,     g_embH);
    cudaGetSymbolAddress((void**)&p_emb_new,  g_emb_new);
    cudaGetSymbolAddress((void**)&p_hidden,   g_hidden);
    cudaGetSymbolAddress((void**)&p_emb_new2, g_emb_new2);
    cudaGetSymbolAddress((void**)&p_residual, g_residual);
    cudaGetSymbolAddress((void**)&p_nodeacc,  g_nodeacc);
    cudaGetSymbolAddress((void**)&p_accRh,    g_accRh);
    cudaGetSymbolAddress((void**)&p_offs,     g_offs);
    cudaGetSymbolAddress((void**)&p_cursor,   g_cursor);
    cudaGetSymbolAddress((void**)&p_WtC,  g_WtC);
    cudaGetSymbolAddress((void**)&p_Wt2,  g_Wt2);
    cudaGetSymbolAddress((void**)&p_WtP,  g_WtP);
    cudaGetSymbolAddress((void**)&p_WtQ,  g_WtQ);
    cudaGetSymbolAddress((void**)&p_biasC, g_biasC);
    cudaGetSymbolAddress((void**)&p_biasP, g_biasP);

    // dynamic smem: words * 4 bytes
    const int SMEM128 = (2 * 128 * 20 + 2 * 128 * 20) * 4;  // 40960
    const int SMEM64  = (2 * 128 * 20 + 2 * 64  * 20) * 4;  // 30720
    cudaFuncSetAttribute(mma_gemm<128>, cudaFuncAttributeMaxDynamicSharedMemorySize, SMEM128);
    cudaFuncSetAttribute(mma_gemm<64>,  cudaFuncAttributeMaxDynamicSharedMemorySize, SMEM64);

    const int Mtiles = (N + 127) / 128;   // 235
    const int n4 = N * FEAT / 4;

    // 0: CSR offsets
    scan_offsets<<<1, 1024>>>(node_deg, p_offs, p_cursor, N);
    // 1: CSR fill
    csr_fill<<<(NINC + 255) / 256, 256>>>(inc_node, inc_edge, inc_slot, NINC);
    // 2: mega-prep (transposes->fp16 + biases + emb->fp16)
    prep_all<<<614 + (n4 + 255) / 256, 256>>>(embedding, p2W1, p2W2, aW, pW, qW,
                                              p2b1, ab, pb, n4);
    // 3 (ncu target): merged G2+G4: [hidden(h) | residual(f)] = relu(embH @ WtC^T + biasC)
    mma_gemm<128><<<dim3(NC / 128, Mtiles), 256, SMEM128>>>(
        p_embH, p_WtC, p_biasC, (float*)p_hidden, p_residual, N, NC, FEAT, 3,
        nullptr, nullptr, nullptr);
    // 4: G1 emb_new = embH @ pW^T + biasP                              [N x 64] f32
    mma_gemm<64><<<dim3(1, Mtiles), 256, SMEM64>>>(
        p_embH, p_WtP, p_biasP, p_emb_new, nullptr, N, RANK, FEAT, 0,
        nullptr, nullptr, nullptr);
    // 5: G3 emb_new2 = hidden @ p2W2 + p2b2                            [N x 256] f32
    mma_gemm<128><<<dim3(OUTD / 128, Mtiles), 256, SMEM128>>>(
        p_hidden, p_Wt2, p2b2, p_emb_new2, nullptr, N, OUTD, HID, 0,
        nullptr, nullptr, nullptr);
    // 6: edge-level tanh(ee) + relu(esum2)
    edge_kernel<<<(E + 1) / 2, 256>>>(global_emb, edge_nodes, edge_size, node_deg, E);
    // 7: node-major gather
    node_gather<<<N, 256>>>();
    // 8: final fused GEMM: out = relu((accRh@qW^T + acc256)/deg + qb) + residual
    mma_gemm<128><<<dim3(OUTD / 128, Mtiles), 256, SMEM128>>>(
        p_accRh, p_WtQ, qb, (float*)d_out, nullptr, N, OUTD, RANK, 2,
        p_nodeacc, p_residual, node_deg);
}

// round 12
// speedup vs baseline: 1.2664x; 1.0407x over previous
#include <cuda_runtime.h>
#include <cuda_fp16.h>
#include <math.h>
#include <stdint.h>

// Problem constants
#define NN   30000
#define NE   60000
#define FEAT 256
#define HID  1024
#define OUTD 256
#define RANK 64
#define NC   1280   // HID + OUTD (merged G2+G4)

// ---------------- scratch (device globals) ----------------
__device__ __half g_embH   [NN * FEAT];
__device__ float  g_emb_new[NN * RANK];
__device__ __half g_hidden [NN * HID];
__device__ float  g_emb_new2[NN * OUTD];
__device__ float  g_residual[NN * OUTD];
__device__ float  g_tee     [NE * 4 * RANK];
__device__ float  g_esum2   [NE * OUTD];
__device__ float  g_nodeacc [NN * OUTD];
__device__ __half g_accRh   [NN * RANK];
__device__ int    g_offs    [NN + 1];
__device__ int    g_cursor  [NN];
__device__ int    g_csr     [NE * 4];
// K-major fp16 weights
__device__ __half g_WtC [NC * FEAT];
__device__ __half g_Wt2 [OUTD * HID];
__device__ __half g_WtP [RANK * FEAT];
__device__ __half g_WtQ [OUTD * RANK];
__device__ float  g_biasC [NC];
__device__ float  g_biasP [RANK];

// ---------------- helpers ----------------
__device__ __forceinline__ uint32_t smem_u32(const void* p) {
    uint32_t a;
    asm("{ .reg .u64 t; cvta.to.shared.u64 t, %1; cvt.u32.u64 %0, t; }" : "=r"(a) : "l"(p));
    return a;
}
__device__ __forceinline__ uint32_t h2_as_u32(__half2 h) {
    uint32_t u;
    memcpy(&u, &h, 4);
    return u;
}
__device__ __forceinline__ void cp16(uint32_t dst, const void* src, int szbytes) {
    asm volatile("cp.async.ca.shared.global [%0], [%1], 16, %2;"
                 :: "r"(dst), "l"(src), "r"(szbytes) : "memory");
}
#define CP_COMMIT() asm volatile("cp.async.commit_group;" ::: "memory")
#define CP_WAIT(n)  asm volatile("cp.async.wait_group %0;" :: "n"(n) : "memory")

__device__ __forceinline__ void mma16n8k16(float* d, const uint32_t* a, const uint32_t* b) {
    asm volatile(
        "mma.sync.aligned.m16n8k16.row.col.f32.f16.f16.f32 "
        "{%0,%1,%2,%3}, {%4,%5,%6,%7}, {%8,%9}, {%0,%1,%2,%3};"
        : "+f"(d[0]), "+f"(d[1]), "+f"(d[2]), "+f"(d[3])
        : "r"(a[0]), "r"(a[1]), "r"(a[2]), "r"(a[3]), "r"(b[0]), "r"(b[1]));
}
__device__ __forceinline__ void ldsm_x4(uint32_t* r, uint32_t addr) {
    asm volatile("ldmatrix.sync.aligned.m8n8.x4.shared.b16 {%0,%1,%2,%3}, [%4];"
        : "=r"(r[0]), "=r"(r[1]), "=r"(r[2]), "=r"(r[3]) : "r"(addr));
}

// ---------------- mega-prep ----------------
__global__ void prep_all(const float* __restrict__ emb,
                         const float* __restrict__ p2W1, const float* __restrict__ p2W2,
                         const float* __restrict__ aW,   const float* __restrict__ pW,
                         const float* __restrict__ qW,
                         const float* __restrict__ p2b1, const float* __restrict__ ab_,
                         const float* __restrict__ pb_,  int n4)
{
    __shared__ float t[32][33];
    const int bx = blockIdx.x;
    const int tid = threadIdx.x;
    if (bx < 608) {
        const float* W; __half* Wt; int K, N, t0;
        if      (bx < 256) { W = p2W1; Wt = g_WtC;              K = FEAT; N = HID;  t0 = 0;   }
        else if (bx < 512) { W = p2W2; Wt = g_Wt2;              K = HID;  N = OUTD; t0 = 256; }
        else if (bx < 576) { W = aW;   Wt = g_WtC + HID * FEAT; K = FEAT; N = OUTD; t0 = 512; }
        else if (bx < 592) { W = pW;   Wt = g_WtP;              K = FEAT; N = RANK; t0 = 576; }
        else               { W = qW;   Wt = g_WtQ;              K = RANK; N = OUTD; t0 = 592; }
        int tt = bx - t0;
        int tiles_n = N >> 5;
        int n0 = (tt % tiles_n) * 32, k0 = (tt / tiles_n) * 32;
        int tx = tid & 31, ty = tid >> 5;
        for (int i = ty; i < 32; i += 8)
            t[i][tx] = W[(k0 + i) * N + n0 + tx];
        __syncthreads();
        for (int i = ty; i < 32; i += 8)
            Wt[(n0 + i) * K + k0 + tx] = __float2half_rn(t[tx][i]);
    } else if (bx < 614) {
        int i = (bx - 608) * 256 + tid;
        if      (i < HID)        g_biasC[i] = p2b1[i] + p2W1[FEAT * HID + i];
        else if (i < HID + OUTD) g_biasC[i] = ab_[i - HID] + aW[FEAT * OUTD + (i - HID)];
        else if (i < HID + OUTD + RANK) g_biasP[i - HID - OUTD] = pb_[i - HID - OUTD] + pW[FEAT * RANK + (i - HID - OUTD)];
    } else {
        int i = (bx - 614) * 256 + tid;
        if (i < n4) {
            float4 v = ((const float4*)emb)[i];
            uint2 o;
            o.x = h2_as_u32(__floats2half2_rn(v.x, v.y));
            o.y = h2_as_u32(__floats2half2_rn(v.z, v.w));
            ((uint2*)g_embH)[i] = o;
        }
    }
}

// ---------------- CSR offsets ----------------
__global__ __launch_bounds__(1024)
void scan_offsets(const int* __restrict__ deg, int* __restrict__ offs,
                  int* __restrict__ cursor, int N)
{
    constexpr int CE = 32;
    const int tid = threadIdx.x;
    const int start = tid * CE;

    int local = 0;
    if (start < N) {
        #pragma unroll
        for (int j = 0; j < CE; j += 4) {
            int i = start + j;
            if (i + 3 < N) {
                int4 v = *(const int4*)(deg + i);
                local += v.x + v.y + v.z + v.w;
            } else {
                #pragma unroll
                for (int k = 0; k < 4; k++) if (i + k < N) local += deg[i + k];
            }
        }
    }
    __shared__ int warpsum[32];
    int lane = tid & 31, w = tid >> 5;
    int x = local;
    #pragma unroll
    for (int o = 1; o < 32; o <<= 1) { int y = __shfl_up_sync(~0u, x, o); if (lane >= o) x += y; }
    if (lane == 31) warpsum[w] = x;
    __syncthreads();
    if (w == 0) {
        int s = warpsum[lane];
        #pragma unroll
        for (int o = 1; o < 32; o <<= 1) { int y = __shfl_up_sync(~0u, s, o); if (lane >= o) s += y; }
        warpsum[lane] = s;
    }
    __syncthreads();
    int base = x - local + (w > 0 ? warpsum[w - 1] : 0);

    if (start < N) {
        int run = base;
        #pragma unroll
        for (int j = 0; j < CE; j++) {
            int i = start + j;
            if (i < N) { offs[i] = run; cursor[i] = 0; run += deg[i]; }
        }
        if (tid == (N - 1) / CE) offs[N] = run;
    }
}

__global__ void csr_fill(const int* __restrict__ inc_node, const int* __restrict__ inc_edge,
                         const int* __restrict__ inc_slot, int NINC)
{
    int i = blockIdx.x * blockDim.x + threadIdx.x;
    if (i < NINC) {
        int n = inc_node[i];
        int p = atomicAdd(&g_cursor[n], 1);
        g_csr[g_offs[n] + p] = (inc_edge[i] << 2) | inc_slot[i];
    }
}

// ---------------- fp16 tensor-core GEMM (m16n8k16 + ldmatrix) ----------------
// A[M,K] fp16 row-major, Bt[N,K] fp16 K-major; fp32 accumulate.
// CTA tile 128 x NT; 8 warps 4(M)x2(N); warp 32 x NT/2; K-chunk 32.
template<int NT>
__global__ __launch_bounds__(256, 2)
void mma_gemm(const __half* __restrict__ A, const __half* __restrict__ Bt,
              const float* __restrict__ bias,
              float* __restrict__ C, float* __restrict__ C2,
              int M, int N, int K, int mode,
              const float* __restrict__ addSrc, const float* __restrict__ resid,
              const int* __restrict__ degv)
{
    constexpr int STW = 20;                // words per row (40 halves: 32 + 8 pad)
    constexpr int NTILES = NT / 16;
    extern __shared__ uint32_t dyn32[];
    uint32_t* Asm = dyn32;                 // 2 bufs x 128 x STW words
    uint32_t* Bsm = dyn32 + 2 * 128 * STW; // 2 bufs x NT x STW words

    const int tid  = threadIdx.x;
    const int wid  = tid >> 5;
    const int lane = tid & 31;
    const int grp  = lane >> 2;
    const int tig  = lane & 3;
    const int warpM = (wid & 3) * 32;
    const int warpN = (wid >> 2) * (NT / 2);
    const int rowBase = blockIdx.y * 128;
    const int colBase = blockIdx.x * NT;

    float acc[2][NTILES][4];
    #pragma unroll
    for (int mt = 0; mt < 2; mt++)
        #pragma unroll
        for (int nt = 0; nt < NTILES; nt++)
            #pragma unroll
            for (int i = 0; i < 4; i++) acc[mt][nt][i] = 0.f;

    const uint32_t asm_base = smem_u32(Asm);
    const uint32_t bsm_base = smem_u32(Bsm);

    // ldmatrix per-thread row/col (in words) — invariant across chunks
    // A x4 for mt: q=lane>>3: q0 rows0-7 c0; q1 rows8-15 c0; q2 rows0-7 c+4w; q3 rows8-15 c+4w
    const int lrow8 = lane & 7;
    const int a_row_off = lrow8 + (((lane >> 3) & 1) << 3);   // + mt*16 + warpM
    const int a_col_off = ((lane >> 4) << 2);                 // words
    // B x4 for nt pair p: q0 n-rows0-7 c0; q1 rows0-7 c+4w; q2 rows8-15 c0; q3 rows8-15 c+4w
    const int b_row_off = lrow8 + ((lane >> 4) << 3);         // + p*16 + warpN
    const int b_col_off = (((lane >> 3) & 1) << 2);           // words

    auto loadChunk = [&](int c, int buf) {
        #pragma unroll
        for (int i = 0; i < 2; i++) {
            int idx = tid + (i << 8);
            int r = idx >> 2, seg = idx & 3;
            int gr = rowBase + r;
            const __half* src = A + (size_t)gr * K + (c << 5) + (seg << 3);
            uint32_t dst = asm_base + (buf * 128 * STW + r * STW + (seg << 2)) * 4;
            cp16(dst, src, gr < M ? 16 : 0);
        }
        #pragma unroll
        for (int i = 0; i < NT / 64; i++) {
            int idx = tid + (i << 8);
            int r = idx >> 2, seg = idx & 3;
            const __half* src = Bt + (size_t)(colBase + r) * K + (c << 5) + (seg << 3);
            uint32_t dst = bsm_base + (buf * NT * STW + r * STW + (seg << 2)) * 4;
            cp16(dst, src, 16);
        }
        CP_COMMIT();
    };

    const int nch = K >> 5;
    loadChunk(0, 0);

    for (int c = 0; c < nch; ++c) {
        const int buf = c & 1;
        if (c + 1 < nch) { loadChunk(c + 1, buf ^ 1); CP_WAIT(1); }
        else             { CP_WAIT(0); }
        __syncthreads();

        const uint32_t abase = asm_base + (buf * 128 * STW) * 4;
        const uint32_t bbase = bsm_base + (buf * NT * STW) * 4;
        #pragma unroll
        for (int ks = 0; ks < 2; ++ks) {
            const int kw = ks << 3;               // word offset of this k16 step
            uint32_t afr[2][4];
            #pragma unroll
            for (int mt = 0; mt < 2; mt++) {
                uint32_t ad = abase +
                    ((warpM + mt * 16 + a_row_off) * STW + kw + a_col_off) * 4;
                ldsm_x4(afr[mt], ad);
            }
            uint32_t bfr[NTILES][2];
            #pragma unroll
            for (int p = 0; p < NTILES / 2; p++) {
                uint32_t bd = bbase +
                    ((warpN + p * 16 + b_row_off) * STW + kw + b_col_off) * 4;
                uint32_t r4[4];
                ldsm_x4(r4, bd);
                bfr[2 * p][0] = r4[0]; bfr[2 * p][1] = r4[1];
                bfr[2 * p + 1][0] = r4[2]; bfr[2 * p + 1][1] = r4[3];
            }
            #pragma unroll
            for (int mt = 0; mt < 2; mt++)
                #pragma unroll
                for (int nt = 0; nt < NTILES; nt++)
                    mma16n8k16(acc[mt][nt], afr[mt], bfr[nt]);
        }
        __syncthreads();
    }

    #pragma unroll
    for (int mt = 0; mt < 2; mt++) {
        #pragma unroll
        for (int nt = 0; nt < NTILES; nt++) {
            int col = colBase + warpN + nt * 8 + (tig << 1);
            float b0 = bias[col], b1 = bias[col + 1];
            #pragma unroll
            for (int h = 0; h < 2; h++) {
                int row = rowBase + warpM + mt * 16 + grp + h * 8;
                if (row >= M) continue;
                float v0 = acc[mt][nt][2 * h];
                float v1 = acc[mt][nt][2 * h + 1];
                if (mode == 3) {
                    v0 = fmaxf(v0 + b0, 0.f); v1 = fmaxf(v1 + b1, 0.f);
                    if (col < HID) {
                        __half2 hv = __floats2half2_rn(v0, v1);
                        ((uint32_t*)C)[(size_t)row * (HID / 2) + (col >> 1)] = h2_as_u32(hv);
                    } else {
                        *(float2*)(C2 + (size_t)row * OUTD + (col - HID)) = make_float2(v0, v1);
                    }
                } else if (mode == 2) {
                    float rd = 1.0f / (float)degv[row];
                    size_t base = (size_t)row * N + col;
                    v0 = fmaxf((v0 + addSrc[base])     * rd + b0, 0.f) + resid[base];
                    v1 = fmaxf((v1 + addSrc[base + 1]) * rd + b1, 0.f) + resid[base + 1];
                    *(float2*)(C + base) = make_float2(v0, v1);
                } else {
                    *(float2*)(C + (size_t)row * N + col) = make_float2(v0 + b0, v1 + b1);
                }
            }
        }
    }
}

// ---------------- edge kernel: 2 edges per block ----------------
__global__ __launch_bounds__(256)
void edge_kernel(const float* __restrict__ global_emb,
                 const int* __restrict__ edge_nodes,
                 const int* __restrict__ edge_size,
                 const int* __restrict__ node_degree,
                 int E)
{
    __shared__ int   s_nodes[2][4];
    __shared__ float s_scale[2][4];
    __shared__ int   s_size[2];

    const int half = threadIdx.x >> 7;
    const int lt   = threadIdx.x & 127;
    const int e    = blockIdx.x * 2 + half;
    const bool active = (e < E);

    if (active && lt < 4) {
        int sz = edge_size[e];
        if (lt == 0) s_size[half] = sz;
        int n = edge_nodes[e * 4 + lt];
        s_nodes[half][lt] = n;
        float a = (sz == 1) ? 1.0f : (sz <= 3 ? (1.0f / 3.0f) : 0.25f);
        s_scale[half][lt] = __powf((float)node_degree[n], a);
    }
    __syncthreads();
    if (!active) return;

    const int sz = s_size[half];
    const int k = 4 - sz;
    const float invf = (sz == 3) ? 0.5f : (sz == 4 ? (1.0f / 6.0f) : 1.0f);

    if (lt < RANK) {
        const int r = lt;
        float g = global_emb[r];
        float gf = (k == 0) ? 1.0f : (k == 1 ? g : g * g);
        float t[4];
        #pragma unroll
        for (int s = 0; s < 4; s++)
            t[s] = (s < sz) ? s_scale[half][s] * g_emb_new[s_nodes[half][s] * RANK + r] : 1.0f;
        float loo[4];
        loo[0] = t[1] * t[2] * t[3];
        loo[1] = t[0] * t[2] * t[3];
        loo[2] = t[0] * t[1] * t[3];
        loo[3] = t[0] * t[1] * t[2];
        float f = gf * invf;
        unsigned tb = (unsigned)e * (4u * RANK) + r;
        for (int s = 0; s < sz; s++)
            g_tee[tb + (unsigned)s * RANK] = tanhf(loo[s] * f);
    }

    {
        float sum0 = 0.f, sum1 = 0.f;
        for (int s = 0; s < sz; s++) {
            const float* row = g_emb_new2 + (unsigned)s_nodes[half][s] * OUTD;
            sum0 += row[lt];
            sum1 += row[lt + 128];
        }
        unsigned eb = (unsigned)e * OUTD + lt;
        g_esum2[eb]       = fmaxf(sum0, 0.f);
        g_esum2[eb + 128] = fmaxf(sum1, 0.f);
    }
}

// ---------------- node-major gather ----------------
__global__ __launch_bounds__(256)
void node_gather()
{
    int n = blockIdx.x;
    int tid = threadIdx.x;
    int s0 = g_offs[n], s1 = g_offs[n + 1];
    float acc0 = 0.f, acc1 = 0.f;
    float accr0 = 0.f, accr1 = 0.f;
    int j = s0;
    for (; j + 1 < s1; j += 2) {
        int codeA = g_csr[j], codeB = g_csr[j + 1];
        unsigned offA = (unsigned)(codeA >> 2) * OUTD;
        unsigned offB = (unsigned)(codeB >> 2) * OUTD;
        acc0 += g_esum2[offA + tid];
        acc1 += g_esum2[offB + tid];
        if (tid < RANK) {
            accr0 += g_tee[(unsigned)codeA * RANK + tid];
            accr1 += g_tee[(unsigned)codeB * RANK + tid];
        }
    }
    if (j < s1) {
        int code = g_csr[j];
        acc0 += g_esum2[(unsigned)(code >> 2) * OUTD + tid];
        if (tid < RANK) accr0 += g_tee[(unsigned)code * RANK + tid];
    }
    g_nodeacc[(unsigned)n * OUTD + tid] = acc0 + acc1;
    if (tid < RANK) g_accRh[(unsigned)n * RANK + tid] = __float2half_rn(accr0 + accr1);
}

// ---------------- launch ----------------
extern "C" void kernel_launch(void* const* d_in, const int* in_sizes, int n_in,
                              void* d_out, int out_size)
{
    const float* embedding  = (const float*)d_in[0];
    const float* global_emb = (const float*)d_in[1];
    const float* pW         = (const float*)d_in[2];
    const float* pb         = (const float*)d_in[3];
    const float* qW         = (const float*)d_in[4];
    const float* qb         = (const float*)d_in[5];
    const float* p2W1       = (const float*)d_in[6];
    const float* p2b1       = (const float*)d_in[7];
    const float* p2W2       = (const float*)d_in[8];
    const float* p2b2       = (const float*)d_in[9];
    const float* aW         = (const float*)d_in[10];
    const float* ab         = (const float*)d_in[11];
    const int*   edge_nodes = (const int*)d_in[12];
    const int*   edge_size  = (const int*)d_in[14];
    const int*   node_deg   = (const int*)d_in[15];
    const int*   inc_node   = (const int*)d_in[16];
    const int*   inc_edge   = (const int*)d_in[17];
    const int*   inc_slot   = (const int*)d_in[18];

    const int N    = in_sizes[0] / FEAT;
    const int E    = in_sizes[14];
    const int NINC = in_sizes[16];

    __half *p_embH, *p_hidden, *p_accRh, *p_WtC, *p_Wt2, *p_WtP, *p_WtQ;
    float *p_emb_new, *p_emb_new2, *p_residual, *p_nodeacc, *p_biasC, *p_biasP;
    int *p_offs, *p_cursor;
    cudaGetSymbolAddress((void**)&p_embH,     g_embH);
    cudaGetSymbolAddress((void**)&p_emb_new,  g_emb_new);
    cudaGetSymbolAddress((void**)&p_hidden,   g_hidden);
    cudaGetSymbolAddress((void**)&p_emb_new2, g_emb_new2);
    cudaGetSymbolAddress((void**)&p_residual, g_residual);
    cudaGetSymbolAddress((void**)&p_nodeacc,  g_nodeacc);
    cudaGetSymbolAddress((void**)&p_accRh,    g_accRh);
    cudaGetSymbolAddress((void**)&p_offs,     g_offs);
    cudaGetSymbolAddress((void**)&p_cursor,   g_cursor);
    cudaGetSymbolAddress((void**)&p_WtC,  g_WtC);
    cudaGetSymbolAddress((void**)&p_Wt2,  g_Wt2);
    cudaGetSymbolAddress((void**)&p_WtP,  g_WtP);
    cudaGetSymbolAddress((void**)&p_WtQ,  g_WtQ);
    cudaGetSymbolAddress((void**)&p_biasC, g_biasC);
    cudaGetSymbolAddress((void**)&p_biasP, g_biasP);

    const int SMEM128 = (2 * 128 * 20 + 2 * 128 * 20) * 4;  // 40960
    const int SMEM64  = (2 * 128 * 20 + 2 * 64  * 20) * 4;  // 30720
    cudaFuncSetAttribute(mma_gemm<128>, cudaFuncAttributeMaxDynamicSharedMemorySize, SMEM128);
    cudaFuncSetAttribute(mma_gemm<64>,  cudaFuncAttributeMaxDynamicSharedMemorySize, SMEM64);

    const int Mtiles = (N + 127) / 128;   // 235
    const int n4 = N * FEAT / 4;

    // 0: CSR offsets
    scan_offsets<<<1, 1024>>>(node_deg, p_offs, p_cursor, N);
    // 1: CSR fill
    csr_fill<<<(NINC + 255) / 256, 256>>>(inc_node, inc_edge, inc_slot, NINC);
    // 2: mega-prep (transposes->fp16 + biases + emb->fp16)
    prep_all<<<614 + (n4 + 255) / 256, 256>>>(embedding, p2W1, p2W2, aW, pW, qW,
                                              p2b1, ab, pb, n4);
    // 3 (ncu target): merged G2+G4: [hidden(h) | residual(f)] = relu(embH @ WtC^T + biasC)
    mma_gemm<128><<<dim3(NC / 128, Mtiles), 256, SMEM128>>>(
        p_embH, p_WtC, p_biasC, (float*)p_hidden, p_residual, N, NC, FEAT, 3,
        nullptr, nullptr, nullptr);
    // 4: G1 emb_new = embH @ pW^T + biasP                              [N x 64] f32
    mma_gemm<64><<<dim3(1, Mtiles), 256, SMEM64>>>(
        p_embH, p_WtP, p_biasP, p_emb_new, nullptr, N, RANK, FEAT, 0,
        nullptr, nullptr, nullptr);
    // 5: G3 emb_new2 = hidden @ p2W2 + p2b2                            [N x 256] f32
    mma_gemm<128><<<dim3(OUTD / 128, Mtiles), 256, SMEM128>>>(
        p_hidden, p_Wt2, p2b2, p_emb_new2, nullptr, N, OUTD, HID, 0,
        nullptr, nullptr, nullptr);
    // 6: edge-level tanh(ee) + relu(esum2)
    edge_kernel<<<(E + 1) / 2, 256>>>(global_emb, edge_nodes, edge_size, node_deg, E);
    // 7: node-major gather
    node_gather<<<N, 256>>>();
    // 8: final fused GEMM: out = relu((accRh@qW^T + acc256)/deg + qb) + residual
    mma_gemm<128><<<dim3(OUTD / 128, Mtiles), 256, SMEM128>>>(
        p_accRh, p_WtQ, qb, (float*)d_out, nullptr, N, OUTD, RANK, 2,
        p_nodeacc, p_residual, node_deg);
}

// round 13
// speedup vs baseline: 1.3314x; 1.0514x over previous
#include <cuda_runtime.h>
#include <cuda_fp16.h>
#include <math.h>
#include <stdint.h>

// Problem constants
#define NN   30000
#define NE   60000
#define FEAT 256
#define HID  1024
#define OUTD 256
#define RANK 64
#define NC   1280   // HID + OUTD (merged G2+G4)

// ---------------- scratch (device globals) ----------------
__device__ __half g_embH    [NN * FEAT];
__device__ float  g_emb_new [NN * RANK];     // fp32 (precision-critical: powers)
__device__ __half g_hidden  [NN * HID];
__device__ __half g_emb_new2[NN * OUTD];     // fp16
__device__ float  g_residual[NN * OUTD];
__device__ __half g_tee     [NE * 4 * RANK]; // fp16 tanh(ee)
__device__ __half g_esum2   [NE * OUTD];     // fp16 relu(esum2)
__device__ float  g_nodeacc [NN * OUTD];
__device__ __half g_accRh   [NN * RANK];
__device__ int    g_offs    [NN + 1];
__device__ int    g_cursor  [NN];
__device__ int    g_csr     [NE * 4];
// K-major fp16 weights
__device__ __half g_WtC [NC * FEAT];
__device__ __half g_Wt2 [OUTD * HID];
__device__ __half g_WtP [RANK * FEAT];
__device__ __half g_WtQ [OUTD * RANK];
__device__ float  g_biasC [NC];
__device__ float  g_biasP [RANK];

// ---------------- helpers ----------------
__device__ __forceinline__ uint32_t smem_u32(const void* p) {
    uint32_t a;
    asm("{ .reg .u64 t; cvta.to.shared.u64 t, %1; cvt.u32.u64 %0, t; }" : "=r"(a) : "l"(p));
    return a;
}
__device__ __forceinline__ uint32_t h2_as_u32(__half2 h) {
    uint32_t u;
    memcpy(&u, &h, 4);
    return u;
}
__device__ __forceinline__ void cp16(uint32_t dst, const void* src, int szbytes) {
    asm volatile("cp.async.ca.shared.global [%0], [%1], 16, %2;"
                 :: "r"(dst), "l"(src), "r"(szbytes) : "memory");
}
#define CP_COMMIT() asm volatile("cp.async.commit_group;" ::: "memory")
#define CP_WAIT(n)  asm volatile("cp.async.wait_group %0;" :: "n"(n) : "memory")

__device__ __forceinline__ void mma16n8k16(float* d, const uint32_t* a, const uint32_t* b) {
    asm volatile(
        "mma.sync.aligned.m16n8k16.row.col.f32.f16.f16.f32 "
        "{%0,%1,%2,%3}, {%4,%5,%6,%7}, {%8,%9}, {%0,%1,%2,%3};"
        : "+f"(d[0]), "+f"(d[1]), "+f"(d[2]), "+f"(d[3])
        : "r"(a[0]), "r"(a[1]), "r"(a[2]), "r"(a[3]), "r"(b[0]), "r"(b[1]));
}
__device__ __forceinline__ void ldsm_x4(uint32_t* r, uint32_t addr) {
    asm volatile("ldmatrix.sync.aligned.m8n8.x4.shared.b16 {%0,%1,%2,%3}, [%4];"
        : "=r"(r[0]), "=r"(r[1]), "=r"(r[2]), "=r"(r[3]) : "r"(addr));
}

// ---------------- mega-prep ----------------
__global__ void prep_all(const float* __restrict__ emb,
                         const float* __restrict__ p2W1, const float* __restrict__ p2W2,
                         const float* __restrict__ aW,   const float* __restrict__ pW,
                         const float* __restrict__ qW,
                         const float* __restrict__ p2b1, const float* __restrict__ ab_,
                         const float* __restrict__ pb_,  int n4)
{
    __shared__ float t[32][33];
    const int bx = blockIdx.x;
    const int tid = threadIdx.x;
    if (bx < 608) {
        const float* W; __half* Wt; int K, N, t0;
        if      (bx < 256) { W = p2W1; Wt = g_WtC;              K = FEAT; N = HID;  t0 = 0;   }
        else if (bx < 512) { W = p2W2; Wt = g_Wt2;              K = HID;  N = OUTD; t0 = 256; }
        else if (bx < 576) { W = aW;   Wt = g_WtC + HID * FEAT; K = FEAT; N = OUTD; t0 = 512; }
        else if (bx < 592) { W = pW;   Wt = g_WtP;              K = FEAT; N = RANK; t0 = 576; }
        else               { W = qW;   Wt = g_WtQ;              K = RANK; N = OUTD; t0 = 592; }
        int tt = bx - t0;
        int tiles_n = N >> 5;
        int n0 = (tt % tiles_n) * 32, k0 = (tt / tiles_n) * 32;
        int tx = tid & 31, ty = tid >> 5;
        for (int i = ty; i < 32; i += 8)
            t[i][tx] = W[(k0 + i) * N + n0 + tx];
        __syncthreads();
        for (int i = ty; i < 32; i += 8)
            Wt[(n0 + i) * K + k0 + tx] = __float2half_rn(t[tx][i]);
    } else if (bx < 614) {
        int i = (bx - 608) * 256 + tid;
        if      (i < HID)        g_biasC[i] = p2b1[i] + p2W1[FEAT * HID + i];
        else if (i < HID + OUTD) g_biasC[i] = ab_[i - HID] + aW[FEAT * OUTD + (i - HID)];
        else if (i < HID + OUTD + RANK) g_biasP[i - HID - OUTD] = pb_[i - HID - OUTD] + pW[FEAT * RANK + (i - HID - OUTD)];
    } else {
        int i = (bx - 614) * 256 + tid;
        if (i < n4) {
            float4 v = ((const float4*)emb)[i];
            uint2 o;
            o.x = h2_as_u32(__floats2half2_rn(v.x, v.y));
            o.y = h2_as_u32(__floats2half2_rn(v.z, v.w));
            ((uint2*)g_embH)[i] = o;
        }
    }
}

// ---------------- CSR offsets ----------------
__global__ __launch_bounds__(1024)
void scan_offsets(const int* __restrict__ deg, int* __restrict__ offs,
                  int* __restrict__ cursor, int N)
{
    constexpr int CE = 32;
    const int tid = threadIdx.x;
    const int start = tid * CE;

    int local = 0;
    if (start < N) {
        #pragma unroll
        for (int j = 0; j < CE; j += 4) {
            int i = start + j;
            if (i + 3 < N) {
                int4 v = *(const int4*)(deg + i);
                local += v.x + v.y + v.z + v.w;
            } else {
                #pragma unroll
                for (int k = 0; k < 4; k++) if (i + k < N) local += deg[i + k];
            }
        }
    }
    __shared__ int warpsum[32];
    int lane = tid & 31, w = tid >> 5;
    int x = local;
    #pragma unroll
    for (int o = 1; o < 32; o <<= 1) { int y = __shfl_up_sync(~0u, x, o); if (lane >= o) x += y; }
    if (lane == 31) warpsum[w] = x;
    __syncthreads();
    if (w == 0) {
        int s = warpsum[lane];
        #pragma unroll
        for (int o = 1; o < 32; o <<= 1) { int y = __shfl_up_sync(~0u, s, o); if (lane >= o) s += y; }
        warpsum[lane] = s;
    }
    __syncthreads();
    int base = x - local + (w > 0 ? warpsum[w - 1] : 0);

    if (start < N) {
        int run = base;
        #pragma unroll
        for (int j = 0; j < CE; j++) {
            int i = start + j;
            if (i < N) { offs[i] = run; cursor[i] = 0; run += deg[i]; }
        }
        if (tid == (N - 1) / CE) offs[N] = run;
    }
}

__global__ void csr_fill(const int* __restrict__ inc_node, const int* __restrict__ inc_edge,
                         const int* __restrict__ inc_slot, int NINC)
{
    int i = blockIdx.x * blockDim.x + threadIdx.x;
    if (i < NINC) {
        int n = inc_node[i];
        int p = atomicAdd(&g_cursor[n], 1);
        g_csr[g_offs[n] + p] = (inc_edge[i] << 2) | inc_slot[i];
    }
}

// ---------------- fp16 tensor-core GEMM (m16n8k16 + ldmatrix) ----------------
// mode 0: C(f32) = acc + bias
// mode 2: C(f32) = relu((acc + addSrc)/deg + bias) + resid
// mode 3: col<HID -> relu -> half2 (stride HID); else relu -> f32 C2 (stride OUTD)
// mode 4: C = half2(acc + bias), stride N (fp16 output, no relu)
template<int NT>
__global__ __launch_bounds__(256, 2)
void mma_gemm(const __half* __restrict__ A, const __half* __restrict__ Bt,
              const float* __restrict__ bias,
              float* __restrict__ C, float* __restrict__ C2,
              int M, int N, int K, int mode,
              const float* __restrict__ addSrc, const float* __restrict__ resid,
              const int* __restrict__ degv)
{
    constexpr int STW = 20;
    constexpr int NTILES = NT / 16;
    extern __shared__ uint32_t dyn32[];
    uint32_t* Asm = dyn32;
    uint32_t* Bsm = dyn32 + 2 * 128 * STW;

    const int tid  = threadIdx.x;
    const int wid  = tid >> 5;
    const int lane = tid & 31;
    const int grp  = lane >> 2;
    const int tig  = lane & 3;
    const int warpM = (wid & 3) * 32;
    const int warpN = (wid >> 2) * (NT / 2);
    const int rowBase = blockIdx.y * 128;
    const int colBase = blockIdx.x * NT;

    float acc[2][NTILES][4];
    #pragma unroll
    for (int mt = 0; mt < 2; mt++)
        #pragma unroll
        for (int nt = 0; nt < NTILES; nt++)
            #pragma unroll
            for (int i = 0; i < 4; i++) acc[mt][nt][i] = 0.f;

    const uint32_t asm_base = smem_u32(Asm);
    const uint32_t bsm_base = smem_u32(Bsm);

    const int lrow8 = lane & 7;
    const int a_row_off = lrow8 + (((lane >> 3) & 1) << 3);
    const int a_col_off = ((lane >> 4) << 2);
    const int b_row_off = lrow8 + ((lane >> 4) << 3);
    const int b_col_off = (((lane >> 3) & 1) << 2);

    auto loadChunk = [&](int c, int buf) {
        #pragma unroll
        for (int i = 0; i < 2; i++) {
            int idx = tid + (i << 8);
            int r = idx >> 2, seg = idx & 3;
            int gr = rowBase + r;
            const __half* src = A + (size_t)gr * K + (c << 5) + (seg << 3);
            uint32_t dst = asm_base + (buf * 128 * STW + r * STW + (seg << 2)) * 4;
            cp16(dst, src, gr < M ? 16 : 0);
        }
        #pragma unroll
        for (int i = 0; i < NT / 64; i++) {
            int idx = tid + (i << 8);
            int r = idx >> 2, seg = idx & 3;
            const __half* src = Bt + (size_t)(colBase + r) * K + (c << 5) + (seg << 3);
            uint32_t dst = bsm_base + (buf * NT * STW + r * STW + (seg << 2)) * 4;
            cp16(dst, src, 16);
        }
        CP_COMMIT();
    };

    const int nch = K >> 5;
    loadChunk(0, 0);

    for (int c = 0; c < nch; ++c) {
        const int buf = c & 1;
        if (c + 1 < nch) { loadChunk(c + 1, buf ^ 1); CP_WAIT(1); }
        else             { CP_WAIT(0); }
        __syncthreads();

        const uint32_t abase = asm_base + (buf * 128 * STW) * 4;
        const uint32_t bbase = bsm_base + (buf * NT * STW) * 4;
        #pragma unroll
        for (int ks = 0; ks < 2; ++ks) {
            const int kw = ks << 3;
            uint32_t afr[2][4];
            #pragma unroll
            for (int mt = 0; mt < 2; mt++) {
                uint32_t ad = abase +
                    ((warpM + mt * 16 + a_row_off) * STW + kw + a_col_off) * 4;
                ldsm_x4(afr[mt], ad);
            }
            uint32_t bfr[NTILES][2];
            #pragma unroll
            for (int p = 0; p < NTILES / 2; p++) {
                uint32_t bd = bbase +
                    ((warpN + p * 16 + b_row_off) * STW + kw + b_col_off) * 4;
                uint32_t r4[4];
                ldsm_x4(r4, bd);
                bfr[2 * p][0] = r4[0]; bfr[2 * p][1] = r4[1];
                bfr[2 * p + 1][0] = r4[2]; bfr[2 * p + 1][1] = r4[3];
            }
            #pragma unroll
            for (int mt = 0; mt < 2; mt++)
                #pragma unroll
                for (int nt = 0; nt < NTILES; nt++)
                    mma16n8k16(acc[mt][nt], afr[mt], bfr[nt]);
        }
        __syncthreads();
    }

    #pragma unroll
    for (int mt = 0; mt < 2; mt++) {
        #pragma unroll
        for (int nt = 0; nt < NTILES; nt++) {
            int col = colBase + warpN + nt * 8 + (tig << 1);
            float b0 = bias[col], b1 = bias[col + 1];
            #pragma unroll
            for (int h = 0; h < 2; h++) {
                int row = rowBase + warpM + mt * 16 + grp + h * 8;
                if (row >= M) continue;
                float v0 = acc[mt][nt][2 * h];
                float v1 = acc[mt][nt][2 * h + 1];
                if (mode == 3) {
                    v0 = fmaxf(v0 + b0, 0.f); v1 = fmaxf(v1 + b1, 0.f);
                    if (col < HID) {
                        ((uint32_t*)C)[(size_t)row * (HID / 2) + (col >> 1)] =
                            h2_as_u32(__floats2half2_rn(v0, v1));
                    } else {
                        *(float2*)(C2 + (size_t)row * OUTD + (col - HID)) = make_float2(v0, v1);
                    }
                } else if (mode == 4) {
                    ((uint32_t*)C)[(size_t)row * (N / 2) + (col >> 1)] =
                        h2_as_u32(__floats2half2_rn(v0 + b0, v1 + b1));
                } else if (mode == 2) {
                    float rd = 1.0f / (float)degv[row];
                    size_t base = (size_t)row * N + col;
                    v0 = fmaxf((v0 + addSrc[base])     * rd + b0, 0.f) + resid[base];
                    v1 = fmaxf((v1 + addSrc[base + 1]) * rd + b1, 0.f) + resid[base + 1];
                    *(float2*)(C + base) = make_float2(v0, v1);
                } else {
                    *(float2*)(C + (size_t)row * N + col) = make_float2(v0 + b0, v1 + b1);
                }
            }
        }
    }
}

// ---------------- edge kernel: 2 edges per block; fp16 in/out for esum2 path ----------------
__global__ __launch_bounds__(256)
void edge_kernel(const float* __restrict__ global_emb,
                 const int* __restrict__ edge_nodes,
                 const int* __restrict__ edge_size,
                 const int* __restrict__ node_degree,
                 int E)
{
    __shared__ int   s_nodes[2][4];
    __shared__ float s_scale[2][4];
    __shared__ int   s_size[2];

    const int half = threadIdx.x >> 7;
    const int lt   = threadIdx.x & 127;
    const int e    = blockIdx.x * 2 + half;
    const bool active = (e < E);

    if (active && lt < 4) {
        int sz = edge_size[e];
        if (lt == 0) s_size[half] = sz;
        int n = edge_nodes[e * 4 + lt];
        s_nodes[half][lt] = n;
        float a = (sz == 1) ? 1.0f : (sz <= 3 ? (1.0f / 3.0f) : 0.25f);
        s_scale[half][lt] = __powf((float)node_degree[n], a);
    }
    __syncthreads();
    if (!active) return;

    const int sz = s_size[half];
    const int k = 4 - sz;
    const float invf = (sz == 3) ? 0.5f : (sz == 4 ? (1.0f / 6.0f) : 1.0f);

    if (lt < RANK) {
        const int r = lt;
        float g = global_emb[r];
        float gf = (k == 0) ? 1.0f : (k == 1 ? g : g * g);
        float t[4];
        #pragma unroll
        for (int s = 0; s < 4; s++)
            t[s] = (s < sz) ? s_scale[half][s] * g_emb_new[s_nodes[half][s] * RANK + r] : 1.0f;
        float loo[4];
        loo[0] = t[1] * t[2] * t[3];
        loo[1] = t[0] * t[2] * t[3];
        loo[2] = t[0] * t[1] * t[3];
        loo[3] = t[0] * t[1] * t[2];
        float f = gf * invf;
        unsigned tb = (unsigned)e * (4u * RANK) + r;
        for (int s = 0; s < sz; s++)
            g_tee[tb + (unsigned)s * RANK] = __float2half_rn(tanhf(loo[s] * f));
    }

    // esum2: each thread handles cols (2lt, 2lt+1) via half2
    {
        float sum0 = 0.f, sum1 = 0.f;
        for (int s = 0; s < sz; s++) {
            const __half2* row = (const __half2*)(g_emb_new2 + (unsigned)s_nodes[half][s] * OUTD);
            float2 v = __half22float2(row[lt]);
            sum0 += v.x;
            sum1 += v.y;
        }
        __half2* out = (__half2*)(g_esum2 + (unsigned)e * OUTD);
        out[lt] = __floats2half2_rn(fmaxf(sum0, 0.f), fmaxf(sum1, 0.f));
    }
}

// ---------------- node-major gather (fp16 sources, fp32 accumulate) ----------------
__global__ __launch_bounds__(256)
void node_gather()
{
    int n = blockIdx.x;
    int tid = threadIdx.x;
    int s0 = g_offs[n], s1 = g_offs[n + 1];
    float acc0 = 0.f, acc1 = 0.f;
    float accr0 = 0.f, accr1 = 0.f;
    int j = s0;
    for (; j + 1 < s1; j += 2) {
        int codeA = g_csr[j], codeB = g_csr[j + 1];
        unsigned offA = (unsigned)(codeA >> 2) * OUTD;
        unsigned offB = (unsigned)(codeB >> 2) * OUTD;
        acc0 += __half2float(g_esum2[offA + tid]);
        acc1 += __half2float(g_esum2[offB + tid]);
        if (tid < RANK) {
            accr0 += __half2float(g_tee[(unsigned)codeA * RANK + tid]);
            accr1 += __half2float(g_tee[(unsigned)codeB * RANK + tid]);
        }
    }
    if (j < s1) {
        int code = g_csr[j];
        acc0 += __half2float(g_esum2[(unsigned)(code >> 2) * OUTD + tid]);
        if (tid < RANK) accr0 += __half2float(g_tee[(unsigned)code * RANK + tid]);
    }
    g_nodeacc[(unsigned)n * OUTD + tid] = acc0 + acc1;
    if (tid < RANK) g_accRh[(unsigned)n * RANK + tid] = __float2half_rn(accr0 + accr1);
}

// ---------------- launch ----------------
extern "C" void kernel_launch(void* const* d_in, const int* in_sizes, int n_in,
                              void* d_out, int out_size)
{
    const float* embedding  = (const float*)d_in[0];
    const float* global_emb = (const float*)d_in[1];
    const float* pW         = (const float*)d_in[2];
    const float* pb         = (const float*)d_in[3];
    const float* qW         = (const float*)d_in[4];
    const float* qb         = (const float*)d_in[5];
    const float* p2W1       = (const float*)d_in[6];
    const float* p2b1       = (const float*)d_in[7];
    const float* p2W2       = (const float*)d_in[8];
    const float* p2b2       = (const float*)d_in[9];
    const float* aW         = (const float*)d_in[10];
    const float* ab         = (const float*)d_in[11];
    const int*   edge_nodes = (const int*)d_in[12];
    const int*   edge_size  = (const int*)d_in[14];
    const int*   node_deg   = (const int*)d_in[15];
    const int*   inc_node   = (const int*)d_in[16];
    const int*   inc_edge   = (const int*)d_in[17];
    const int*   inc_slot   = (const int*)d_in[18];

    const int N    = in_sizes[0] / FEAT;
    const int E    = in_sizes[14];
    const int NINC = in_sizes[16];

    __half *p_embH, *p_hidden, *p_emb_new2, *p_accRh, *p_WtC, *p_Wt2, *p_WtP, *p_WtQ;
    float *p_emb_new, *p_residual, *p_nodeacc, *p_biasC, *p_biasP;
    int *p_offs, *p_cursor;
    cudaGetSymbolAddress((void**)&p_embH,     g_embH);
    cudaGetSymbolAddress((void**)&p_emb_new,  g_emb_new);
    cudaGetSymbolAddress((void**)&p_hidden,   g_hidden);
    cudaGetSymbolAddress((void**)&p_emb_new2, g_emb_new2);
    cudaGetSymbolAddress((void**)&p_residual, g_residual);
    cudaGetSymbolAddress((void**)&p_nodeacc,  g_nodeacc);
    cudaGetSymbolAddress((void**)&p_accRh,    g_accRh);
    cudaGetSymbolAddress((void**)&p_offs,     g_offs);
    cudaGetSymbolAddress((void**)&p_cursor,   g_cursor);
    cudaGetSymbolAddress((void**)&p_WtC,  g_WtC);
    cudaGetSymbolAddress((void**)&p_Wt2,  g_Wt2);
    cudaGetSymbolAddress((void**)&p_WtP,  g_WtP);
    cudaGetSymbolAddress((void**)&p_WtQ,  g_WtQ);
    cudaGetSymbolAddress((void**)&p_biasC, g_biasC);
    cudaGetSymbolAddress((void**)&p_biasP, g_biasP);

    const int SMEM128 = (2 * 128 * 20 + 2 * 128 * 20) * 4;  // 40960
    const int SMEM64  = (2 * 128 * 20 + 2 * 64  * 20) * 4;  // 30720
    cudaFuncSetAttribute(mma_gemm<128>, cudaFuncAttributeMaxDynamicSharedMemorySize, SMEM128);
    cudaFuncSetAttribute(mma_gemm<64>,  cudaFuncAttributeMaxDynamicSharedMemorySize, SMEM64);

    const int Mtiles = (N + 127) / 128;   // 235
    const int n4 = N * FEAT / 4;

    // 0: mega-prep
    prep_all<<<614 + (n4 + 255) / 256, 256>>>(embedding, p2W1, p2W2, aW, pW, qW,
                                              p2b1, ab, pb, n4);
    // 1: merged G2+G4: [hidden(h) | residual(f)] = relu(embH @ WtC^T + biasC)
    mma_gemm<128><<<dim3(NC / 128, Mtiles), 256, SMEM128>>>(
        p_embH, p_WtC, p_biasC, (float*)p_hidden, p_residual, N, NC, FEAT, 3,
        nullptr, nullptr, nullptr);
    // 2: G1 emb_new(f32) = embH @ pW^T + biasP                      [N x 64]
    mma_gemm<64><<<dim3(1, Mtiles), 256, SMEM64>>>(
        p_embH, p_WtP, p_biasP, p_emb_new, nullptr, N, RANK, FEAT, 0,
        nullptr, nullptr, nullptr);
    // 3 (ncu target): G3 emb_new2(h) = hidden @ p2W2 + p2b2          [N x 256]
    mma_gemm<128><<<dim3(OUTD / 128, Mtiles), 256, SMEM128>>>(
        p_hidden, p_Wt2, p2b2, (float*)p_emb_new2, nullptr, N, OUTD, HID, 4,
        nullptr, nullptr, nullptr);
    // 4: CSR offsets
    scan_offsets<<<1, 1024>>>(node_deg, p_offs, p_cursor, N);
    // 5: CSR fill
    csr_fill<<<(NINC + 255) / 256, 256>>>(inc_node, inc_edge, inc_slot, NINC);
    // 6: edge-level tanh(ee)(h) + relu(esum2)(h)
    edge_kernel<<<(E + 1) / 2, 256>>>(global_emb, edge_nodes, edge_size, node_deg, E);
    // 7: node-major gather
    node_gather<<<N, 256>>>();
    // 8: final fused GEMM: out = relu((accRh@qW^T + acc256)/deg + qb) + residual
    mma_gemm<128><<<dim3(OUTD / 128, Mtiles), 256, SMEM128>>>(
        p_accRh, p_WtQ, qb, (float*)d_out, nullptr, N, OUTD, RANK, 2,
        p_nodeacc, p_residual, node_deg);
}